// round 12
// baseline (speedup 1.0000x reference)
#include <cuda_runtime.h>
#include <cuda_fp16.h>

#define NN 50000
#define EE 600000
#define LLM 640
#define HID 128
#define PO 112
#define SD 16

typedef unsigned int uint;

#define PROJ_ITS 20
#define GCN_ITS  4
#define ITER_WORDS 4096
#define PROJ_FRAG_WORDS (PROJ_ITS * ITER_WORDS)
#define GCN_FRAG_WORDS  (GCN_ITS * ITER_WORDS)

// ---------------- scratch (static device globals; no allocation) ------------
__device__ float  g_x[(size_t)NN * HID];
__device__ __align__(16) __half g_xwh[(size_t)NN * HID];
__device__ float  g_dis[NN];
__device__ __align__(16) int g_cnt[NN];
__device__ int    g_rowptr[NN + 1];
__device__ int    g_pos[NN];
__device__ __align__(16) int g_col[EE];
__device__ __align__(16) uint g_WpF[PROJ_FRAG_WORDS];
__device__ __align__(16) uint g_WgF[2][GCN_FRAG_WORDS];

__device__ __forceinline__ uint f2tf32(float x) {
    uint r;
    asm("cvt.rna.tf32.f32 %0, %1;" : "=r"(r) : "f"(x));
    return r;
}
__device__ __forceinline__ float4 h8_to_f4(uint a, uint b) {
    __half2 ha = *(__half2*)&a, hb = *(__half2*)&b;
    float2 fa = __half22float2(ha), fb = __half22float2(hb);
    return make_float4(fa.x, fa.y, fb.x, fb.y);
}

// Paired-B fragment layout (LDS.128-friendly):
//   word = ((npair*4 + k8)*128) + lane*4 + q,  q in 0..3
//   nt = 2*npair + (q>>1),  j = q&1
//   k = it*32 + k8*8 + j*4 + (lane&3),  n = nt*8 + (lane>>2)
__device__ __forceinline__ void frag_coords(int word, int& k_off, int& n) {
    int blk128 = word >> 7, rem = word & 127;
    int npair = blk128 >> 2, k8 = blk128 & 3;
    int lane = rem >> 2, q = rem & 3;
    int nt = 2 * npair + (q >> 1);
    int j = q & 1;
    k_off = k8 * 8 + j * 4 + (lane & 3);
    n = nt * 8 + (lane >> 2);
}

// ---------------- prep: proj fragments (main stream) ------------------------
__global__ void prep_proj_k(const float* __restrict__ pW) {
    int i = blockIdx.x * blockDim.x + threadIdx.x;
    if (i < PROJ_FRAG_WORDS) {
        int it = i >> 12, word = i & 4095;
        int ko, n;
        frag_coords(word, ko, n);
        int k = it * 32 + ko;
        float v = (n < PO) ? pW[k * PO + n] : 0.0f;
        g_WpF[i] = f2tf32(v);
    }
}

// ---------------- prep: gcn fragments (side stream) -------------------------
__global__ void prep_gcn_k(const float* __restrict__ gW) {
    int i = blockIdx.x * blockDim.x + threadIdx.x;
    if (i < 2 * GCN_FRAG_WORDS) {
        int layer = i >> 14;
        int w = i & (GCN_FRAG_WORDS - 1);
        int it = w >> 12, word = w & 4095;
        int ko, n;
        frag_coords(word, ko, n);
        int k = it * 32 + ko;
        g_WgF[layer][w] = f2tf32(gW[(size_t)layer * HID * HID + k * HID + n]);
    }
}

// ---------------- zero counters (side stream) -------------------------------
__global__ void zero_cnt_k() {
    int i = blockIdx.x * blockDim.x + threadIdx.x;
    if (i < NN) g_cnt[i] = 0;
}

// ---------------- CSR build (side stream) -----------------------------------
__global__ void count_k(const int* __restrict__ dst) {
    int e0 = (blockIdx.x * blockDim.x + threadIdx.x) * 4;
    if (e0 < EE) {
        int4 d = *(const int4*)(dst + e0);
        atomicAdd(&g_cnt[d.x], 1);
        atomicAdd(&g_cnt[d.y], 1);
        atomicAdd(&g_cnt[d.z], 1);
        atomicAdd(&g_cnt[d.w], 1);
    }
}

__global__ void scan_k() {
    __shared__ int warp_tot[32];
    __shared__ int carry_s;
    int tid = threadIdx.x, lane = tid & 31, w = tid >> 5;
    if (tid == 0) { carry_s = 0; g_rowptr[0] = 0; }
    __syncthreads();
    for (int base = 0; base < NN; base += 4096) {
        int i0 = base + tid * 4;
        int4 v = make_int4(0, 0, 0, 0);
        if (i0 < NN) v = *(const int4*)(g_cnt + i0);
        int s = v.x + v.y + v.z + v.w;
        int x = s;
        #pragma unroll
        for (int o = 1; o < 32; o <<= 1) {
            int y = __shfl_up_sync(0xffffffffu, x, o);
            if (lane >= o) x += y;
        }
        if (lane == 31) warp_tot[w] = x;
        __syncthreads();
        if (w == 0) {
            int t = warp_tot[lane];
            #pragma unroll
            for (int o = 1; o < 32; o <<= 1) {
                int y = __shfl_up_sync(0xffffffffu, t, o);
                if (lane >= o) t += y;
            }
            warp_tot[lane] = t;
        }
        __syncthreads();
        int woff = (w > 0) ? warp_tot[w - 1] : 0;
        int incl = x + woff + carry_s;
        int excl = incl - s;
        if (i0 < NN) {
            int p0 = excl + v.x, p1 = p0 + v.y, p2 = p1 + v.z, p3 = p2 + v.w;
            g_rowptr[i0 + 1] = p0; g_rowptr[i0 + 2] = p1;
            g_rowptr[i0 + 3] = p2; g_rowptr[i0 + 4] = p3;
            g_pos[i0] = excl; g_pos[i0 + 1] = p0; g_pos[i0 + 2] = p1; g_pos[i0 + 3] = p2;
            g_dis[i0 + 0] = rsqrtf(1.0f + (float)v.x);
            g_dis[i0 + 1] = rsqrtf(1.0f + (float)v.y);
            g_dis[i0 + 2] = rsqrtf(1.0f + (float)v.z);
            g_dis[i0 + 3] = rsqrtf(1.0f + (float)v.w);
        }
        __syncthreads();
        if (tid == 1023) carry_s = incl;
        __syncthreads();
    }
}

__global__ void fill_k(const int* __restrict__ src, const int* __restrict__ dst) {
    int e0 = (blockIdx.x * blockDim.x + threadIdx.x) * 4;
    if (e0 < EE) {
        int4 d = *(const int4*)(dst + e0);
        int4 s = *(const int4*)(src + e0);
        int p0 = atomicAdd(&g_pos[d.x], 1);
        int p1 = atomicAdd(&g_pos[d.y], 1);
        int p2 = atomicAdd(&g_pos[d.z], 1);
        int p3 = atomicAdd(&g_pos[d.w], 1);
        g_col[p0] = s.x; g_col[p1] = s.y; g_col[p2] = s.z; g_col[p3] = s.w;
    }
}

// ---------------- tf32 mma GEMM, double-buffered, cp.async B ----------------
#define BSA 132
#define ASZ (32 * BSA)
#define BSZ 4096

template<int K, int LDA, bool PROJ>
__global__ __launch_bounds__(256, 2) void mma_gemm_k(const float* __restrict__ A,
                                                     const uint* __restrict__ WF,
                                                     const float* __restrict__ bias,
                                                     const int* __restrict__ ids,
                                                     const float* __restrict__ emb,
                                                     float* __restrict__ outf,
                                                     __half* __restrict__ outh) {
    __shared__ __align__(16) uint As[2][ASZ];
    __shared__ __align__(16) uint Bs[2][BSZ];
    int tid = threadIdx.x;
    int lane = tid & 31, wid = tid >> 5;
    int warp_m = wid >> 2;
    int warp_n = wid & 3;
    int row0 = blockIdx.x * 128;
    const int NT = K / 32;

    float acc[4][4][4];
    #pragma unroll
    for (int mt = 0; mt < 4; mt++)
        #pragma unroll
        for (int nt = 0; nt < 4; nt++)
            #pragma unroll
            for (int j = 0; j < 4; j++) acc[mt][nt][j] = 0.0f;

    float4 va[4];

    auto loadA = [&](int k0) {
        #pragma unroll
        for (int i = 0; i < 4; i++) {
            int f = tid + i * 256;
            int r = f >> 3, c = (f & 7) * 4;
            int gr = row0 + r;
            va[i] = make_float4(0.f, 0.f, 0.f, 0.f);
            if (gr < NN) va[i] = *(const float4*)(A + (size_t)gr * LDA + k0 + c);
        }
    };
    auto storeA = [&](int buf) {
        #pragma unroll
        for (int i = 0; i < 4; i++) {
            int f = tid + i * 256;
            int r = f >> 3, c = (f & 7) * 4;
            int mtile = r >> 4, rloc = r & 15;
            int j = (rloc >> 3) + 2 * ((c >> 2) & 1);
            int tb = (rloc & 7) * 4;
            uint* dst = As[buf] + ((mtile << 2) + (c >> 3)) * BSA + j;
            dst[(tb + 0) * 4] = __float_as_uint(va[i].x);
            dst[(tb + 1) * 4] = __float_as_uint(va[i].y);
            dst[(tb + 2) * 4] = __float_as_uint(va[i].z);
            dst[(tb + 3) * 4] = __float_as_uint(va[i].w);
        }
    };
    auto stageB = [&](int it, int buf) {
        const uint* src = WF + (size_t)it * ITER_WORDS + tid * 16;
        uint sm = (uint)__cvta_generic_to_shared(Bs[buf] + tid * 16);
        #pragma unroll
        for (int i = 0; i < 4; i++)
            asm volatile("cp.async.ca.shared.global [%0], [%1], 16;"
                         :: "r"(sm + i * 16), "l"(src + i * 4));
        asm volatile("cp.async.commit_group;");
    };

    loadA(0);
    stageB(0, 0);
    storeA(0);
    asm volatile("cp.async.wait_group 0;" ::: "memory");
    __syncthreads();

    for (int it = 0; it < NT; it++) {
        int cur = it & 1;
        if (it + 1 < NT) {
            stageB(it + 1, cur ^ 1);
            loadA((it + 1) * 32);
        }

        #pragma unroll
        for (int k8 = 0; k8 < 4; k8++) {
            uint4 a[4];
            uint2 b[4];
            #pragma unroll
            for (int mt = 0; mt < 4; mt++)
                a[mt] = *(const uint4*)(As[cur] + (((warp_m * 4 + mt) << 2) + k8) * BSA + lane * 4);
            // paired B: one LDS.128 covers two adjacent ntile fragments
            #pragma unroll
            for (int p = 0; p < 2; p++) {
                uint4 bb = *(const uint4*)(Bs[cur] + ((((warp_n * 2 + p) << 2) + k8) << 7) + lane * 4);
                b[2 * p]     = make_uint2(bb.x, bb.y);
                b[2 * p + 1] = make_uint2(bb.z, bb.w);
            }
            #pragma unroll
            for (int mt = 0; mt < 4; mt++)
                #pragma unroll
                for (int nt = 0; nt < 4; nt++) {
                    asm volatile(
                        "mma.sync.aligned.m16n8k8.row.col.f32.tf32.tf32.f32 "
                        "{%0,%1,%2,%3}, {%4,%5,%6,%7}, {%8,%9}, {%0,%1,%2,%3};"
                        : "+f"(acc[mt][nt][0]), "+f"(acc[mt][nt][1]),
                          "+f"(acc[mt][nt][2]), "+f"(acc[mt][nt][3])
                        : "r"(a[mt].x), "r"(a[mt].y), "r"(a[mt].z), "r"(a[mt].w),
                          "r"(b[nt].x), "r"(b[nt].y));
                }
        }

        if (it + 1 < NT) {
            storeA(cur ^ 1);
            asm volatile("cp.async.wait_group 0;" ::: "memory");
            __syncthreads();
        }
    }

    #pragma unroll
    for (int mt = 0; mt < 4; mt++) {
        int gr0 = row0 + warp_m * 64 + mt * 16 + (lane >> 2);
        int gr1 = gr0 + 8;
        float s0 = 1.f, s1 = 1.f;
        if (!PROJ) {
            if (gr0 < NN) s0 = g_dis[gr0];
            if (gr1 < NN) s1 = g_dis[gr1];
        }
        #pragma unroll
        for (int nt = 0; nt < 4; nt++) {
            int col = warp_n * 32 + nt * 8 + (lane & 3) * 2;
            if (PROJ) {
                if (col < PO) {
                    float b0 = bias[col], b1 = bias[col + 1];
                    if (gr0 < NN)
                        *(float2*)(outf + (size_t)gr0 * 128 + col) =
                            make_float2(acc[mt][nt][0] + b0, acc[mt][nt][1] + b1);
                    if (gr1 < NN)
                        *(float2*)(outf + (size_t)gr1 * 128 + col) =
                            make_float2(acc[mt][nt][2] + b0, acc[mt][nt][3] + b1);
                } else {
                    int t = col - PO;
                    if (gr0 < NN) {
                        float2 ev = *(const float2*)(emb + ids[gr0] * SD + t);
                        *(float2*)(outf + (size_t)gr0 * 128 + col) = ev;
                    }
                    if (gr1 < NN) {
                        float2 ev = *(const float2*)(emb + ids[gr1] * SD + t);
                        *(float2*)(outf + (size_t)gr1 * 128 + col) = ev;
                    }
                }
            } else {
                if (gr0 < NN)
                    *(__half2*)(outh + (size_t)gr0 * 128 + col) =
                        __floats2half2_rn(acc[mt][nt][0] * s0, acc[mt][nt][1] * s0);
                if (gr1 < NN)
                    *(__half2*)(outh + (size_t)gr1 * 128 + col) =
                        __floats2half2_rn(acc[mt][nt][2] * s1, acc[mt][nt][3] * s1);
            }
        }
    }
}

// ---------------- aggregation: half-warp per row (2 rows/warp) --------------
template<bool LAST>
__global__ void agg_k(const float* __restrict__ bias,
                      const float* __restrict__ lng,
                      const float* __restrict__ lnb,
                      float* __restrict__ out) {
    int warp = threadIdx.x >> 5, lane = threadIdx.x & 31;
    int half = lane >> 4, hl = lane & 15;
    int row = blockIdx.x * 16 + warp * 2 + half;
    if (row >= NN) return;
    const uint4* xw4 = (const uint4*)g_xwh;
    size_t rb = (size_t)row * 16 + hl;
    uint4 ps = xw4[rb];
    float4 a0 = h8_to_f4(ps.x, ps.y);
    float4 a1 = h8_to_f4(ps.z, ps.w);
    int e = g_rowptr[row], end = g_rowptr[row + 1];
    for (; e + 8 <= end; e += 8) {
        int s0 = g_col[e],     s1 = g_col[e + 1], s2 = g_col[e + 2], s3 = g_col[e + 3];
        int s4 = g_col[e + 4], s5 = g_col[e + 5], s6 = g_col[e + 6], s7 = g_col[e + 7];
        uint4 q0 = xw4[(size_t)s0 * 16 + hl];
        uint4 q1 = xw4[(size_t)s1 * 16 + hl];
        uint4 q2 = xw4[(size_t)s2 * 16 + hl];
        uint4 q3 = xw4[(size_t)s3 * 16 + hl];
        uint4 q4 = xw4[(size_t)s4 * 16 + hl];
        uint4 q5 = xw4[(size_t)s5 * 16 + hl];
        uint4 q6 = xw4[(size_t)s6 * 16 + hl];
        uint4 q7 = xw4[(size_t)s7 * 16 + hl];
        float4 u;
        u = h8_to_f4(q0.x, q0.y); a0.x += u.x; a0.y += u.y; a0.z += u.z; a0.w += u.w;
        u = h8_to_f4(q0.z, q0.w); a1.x += u.x; a1.y += u.y; a1.z += u.z; a1.w += u.w;
        u = h8_to_f4(q1.x, q1.y); a0.x += u.x; a0.y += u.y; a0.z += u.z; a0.w += u.w;
        u = h8_to_f4(q1.z, q1.w); a1.x += u.x; a1.y += u.y; a1.z += u.z; a1.w += u.w;
        u = h8_to_f4(q2.x, q2.y); a0.x += u.x; a0.y += u.y; a0.z += u.z; a0.w += u.w;
        u = h8_to_f4(q2.z, q2.w); a1.x += u.x; a1.y += u.y; a1.z += u.z; a1.w += u.w;
        u = h8_to_f4(q3.x, q3.y); a0.x += u.x; a0.y += u.y; a0.z += u.z; a0.w += u.w;
        u = h8_to_f4(q3.z, q3.w); a1.x += u.x; a1.y += u.y; a1.z += u.z; a1.w += u.w;
        u = h8_to_f4(q4.x, q4.y); a0.x += u.x; a0.y += u.y; a0.z += u.z; a0.w += u.w;
        u = h8_to_f4(q4.z, q4.w); a1.x += u.x; a1.y += u.y; a1.z += u.z; a1.w += u.w;
        u = h8_to_f4(q5.x, q5.y); a0.x += u.x; a0.y += u.y; a0.z += u.z; a0.w += u.w;
        u = h8_to_f4(q5.z, q5.w); a1.x += u.x; a1.y += u.y; a1.z += u.z; a1.w += u.w;
        u = h8_to_f4(q6.x, q6.y); a0.x += u.x; a0.y += u.y; a0.z += u.z; a0.w += u.w;
        u = h8_to_f4(q6.z, q6.w); a1.x += u.x; a1.y += u.y; a1.z += u.z; a1.w += u.w;
        u = h8_to_f4(q7.x, q7.y); a0.x += u.x; a0.y += u.y; a0.z += u.z; a0.w += u.w;
        u = h8_to_f4(q7.z, q7.w); a1.x += u.x; a1.y += u.y; a1.z += u.z; a1.w += u.w;
    }
    for (; e + 4 <= end; e += 4) {
        int s0 = g_col[e], s1 = g_col[e + 1], s2 = g_col[e + 2], s3 = g_col[e + 3];
        uint4 q0 = xw4[(size_t)s0 * 16 + hl];
        uint4 q1 = xw4[(size_t)s1 * 16 + hl];
        uint4 q2 = xw4[(size_t)s2 * 16 + hl];
        uint4 q3 = xw4[(size_t)s3 * 16 + hl];
        float4 u;
        u = h8_to_f4(q0.x, q0.y); a0.x += u.x; a0.y += u.y; a0.z += u.z; a0.w += u.w;
        u = h8_to_f4(q0.z, q0.w); a1.x += u.x; a1.y += u.y; a1.z += u.z; a1.w += u.w;
        u = h8_to_f4(q1.x, q1.y); a0.x += u.x; a0.y += u.y; a0.z += u.z; a0.w += u.w;
        u = h8_to_f4(q1.z, q1.w); a1.x += u.x; a1.y += u.y; a1.z += u.z; a1.w += u.w;
        u = h8_to_f4(q2.x, q2.y); a0.x += u.x; a0.y += u.y; a0.z += u.z; a0.w += u.w;
        u = h8_to_f4(q2.z, q2.w); a1.x += u.x; a1.y += u.y; a1.z += u.z; a1.w += u.w;
        u = h8_to_f4(q3.x, q3.y); a0.x += u.x; a0.y += u.y; a0.z += u.z; a0.w += u.w;
        u = h8_to_f4(q3.z, q3.w); a1.x += u.x; a1.y += u.y; a1.z += u.z; a1.w += u.w;
    }
    for (; e < end; e++) {
        uint4 q = xw4[(size_t)g_col[e] * 16 + hl];
        float4 u;
        u = h8_to_f4(q.x, q.y); a0.x += u.x; a0.y += u.y; a0.z += u.z; a0.w += u.w;
        u = h8_to_f4(q.z, q.w); a1.x += u.x; a1.y += u.y; a1.z += u.z; a1.w += u.w;
    }
    float d = g_dis[row];
    const float4* b4 = (const float4*)bias;
    float4 bb0 = b4[hl * 2], bb1 = b4[hl * 2 + 1];
    const float4* x4 = (const float4*)g_x;
    float4 x0 = x4[(size_t)row * 32 + hl * 2];
    float4 x1 = x4[(size_t)row * 32 + hl * 2 + 1];
    float4 v0, v1;
    v0.x = x0.x + fmaxf(d * a0.x + bb0.x, 0.f);
    v0.y = x0.y + fmaxf(d * a0.y + bb0.y, 0.f);
    v0.z = x0.z + fmaxf(d * a0.z + bb0.z, 0.f);
    v0.w = x0.w + fmaxf(d * a0.w + bb0.w, 0.f);
    v1.x = x1.x + fmaxf(d * a1.x + bb1.x, 0.f);
    v1.y = x1.y + fmaxf(d * a1.y + bb1.y, 0.f);
    v1.z = x1.z + fmaxf(d * a1.z + bb1.z, 0.f);
    v1.w = x1.w + fmaxf(d * a1.w + bb1.w, 0.f);
    if (!LAST) {
        ((float4*)g_x)[(size_t)row * 32 + hl * 2] = v0;
        ((float4*)g_x)[(size_t)row * 32 + hl * 2 + 1] = v1;
    } else {
        float s  = (v0.x + v0.y + v0.z + v0.w) + (v1.x + v1.y + v1.z + v1.w);
        float s2 = (v0.x * v0.x + v0.y * v0.y + v0.z * v0.z + v0.w * v0.w)
                 + (v1.x * v1.x + v1.y * v1.y + v1.z * v1.z + v1.w * v1.w);
        #pragma unroll
        for (int o = 8; o; o >>= 1) {
            s  += __shfl_xor_sync(0xffffffffu, s, o);
            s2 += __shfl_xor_sync(0xffffffffu, s2, o);
        }
        float mean = s * (1.0f / 128.0f);
        float var = s2 * (1.0f / 128.0f) - mean * mean;
        float rstd = rsqrtf(var + 1e-5f);
        const float4* g4 = (const float4*)lng;
        const float4* lb4 = (const float4*)lnb;
        float4 gg0 = g4[hl * 2], gg1 = g4[hl * 2 + 1];
        float4 lb0 = lb4[hl * 2], lb1 = lb4[hl * 2 + 1];
        float4 o0, o1;
        o0.x = (v0.x - mean) * rstd * gg0.x + lb0.x;
        o0.y = (v0.y - mean) * rstd * gg0.y + lb0.y;
        o0.z = (v0.z - mean) * rstd * gg0.z + lb0.z;
        o0.w = (v0.w - mean) * rstd * gg0.w + lb0.w;
        o1.x = (v1.x - mean) * rstd * gg1.x + lb1.x;
        o1.y = (v1.y - mean) * rstd * gg1.y + lb1.y;
        o1.z = (v1.z - mean) * rstd * gg1.z + lb1.z;
        o1.w = (v1.w - mean) * rstd * gg1.w + lb1.w;
        ((float4*)out)[(size_t)row * 32 + hl * 2] = o0;
        ((float4*)out)[(size_t)row * 32 + hl * 2 + 1] = o1;
    }
}

// ---------------- launcher --------------------------------------------------
static cudaStream_t g_s1 = nullptr;
static cudaEvent_t  g_evFork = nullptr, g_evScan = nullptr, g_evFill = nullptr;

extern "C" void kernel_launch(void* const* d_in, const int* in_sizes, int n_in,
                              void* d_out, int out_size) {
    const float* llm = (const float*)d_in[0];
    const int*   ids = (const int*)d_in[1];
    const int*   ei  = (const int*)d_in[2];
    const float* pW  = (const float*)d_in[3];
    const float* pb  = (const float*)d_in[4];
    const float* emb = (const float*)d_in[5];
    const float* gW  = (const float*)d_in[6];
    const float* gb  = (const float*)d_in[7];
    const float* lg  = (const float*)d_in[8];
    const float* lb  = (const float*)d_in[9];
    const int* src = ei;
    const int* dst = ei + EE;

    const int MB = (NN + 127) / 128;
    const int HB = (NN + 15) / 16;
    const int EB4 = (EE / 4 + 255) / 256;

    if (g_s1 == nullptr) {
        cudaStreamCreateWithFlags(&g_s1, cudaStreamNonBlocking);
        cudaEventCreateWithFlags(&g_evFork, cudaEventDisableTiming);
        cudaEventCreateWithFlags(&g_evScan, cudaEventDisableTiming);
        cudaEventCreateWithFlags(&g_evFill, cudaEventDisableTiming);
    }

    float*  d_x  = nullptr; cudaGetSymbolAddress((void**)&d_x,  g_x);
    __half* d_xw = nullptr; cudaGetSymbolAddress((void**)&d_xw, g_xwh);
    uint*   d_WpF = nullptr; cudaGetSymbolAddress((void**)&d_WpF, g_WpF);
    uint*   d_WgF = nullptr; cudaGetSymbolAddress((void**)&d_WgF, g_WgF);

    // ---- fork: GCN frag prep + CSR chain on side stream ----
    cudaEventRecord(g_evFork, 0);
    cudaStreamWaitEvent(g_s1, g_evFork, 0);

    prep_gcn_k<<<(2 * GCN_FRAG_WORDS + 255) / 256, 256, 0, g_s1>>>(gW);
    zero_cnt_k<<<(NN + 255) / 256, 256, 0, g_s1>>>();
    count_k<<<EB4, 256, 0, g_s1>>>(dst);
    scan_k<<<1, 1024, 0, g_s1>>>();
    cudaEventRecord(g_evScan, g_s1);   // covers prep_gcn + scan (dis)
    fill_k<<<EB4, 256, 0, g_s1>>>(src, dst);
    cudaEventRecord(g_evFill, g_s1);

    // ---- main stream: proj frag prep + proj ----
    prep_proj_k<<<(PROJ_FRAG_WORDS + 255) / 256, 256>>>(pW);
    mma_gemm_k<LLM, LLM, true><<<MB, 256>>>(llm, d_WpF, pb, ids, emb, d_x, nullptr);

    cudaStreamWaitEvent(0, g_evScan, 0);
    mma_gemm_k<HID, HID, false><<<MB, 256>>>(d_x, d_WgF, nullptr, nullptr, nullptr,
                                             nullptr, d_xw);
    cudaStreamWaitEvent(0, g_evFill, 0);
    agg_k<false><<<HB, 256>>>(gb, nullptr, nullptr, nullptr);

    mma_gemm_k<HID, HID, false><<<MB, 256>>>(d_x, d_WgF + GCN_FRAG_WORDS, nullptr,
                                             nullptr, nullptr, nullptr, d_xw);
    agg_k<true><<<HB, 256>>>(gb + HID, lg, lb, (float*)d_out);
}

// round 13
// speedup vs baseline: 1.1293x; 1.1293x over previous
#include <cuda_runtime.h>
#include <cuda_fp16.h>

#define NN 50000
#define EE 600000
#define LLM 640
#define HID 128
#define PO 112
#define SD 16

typedef unsigned int uint;

#define PROJ_ITS 20
#define GCN_ITS  4
#define ITER_WORDS 4096
#define PROJ_FRAG_WORDS (PROJ_ITS * ITER_WORDS)
#define GCN_FRAG_WORDS  (GCN_ITS * ITER_WORDS)

#define SCAN_CHUNK 4096
#define NSCAN ((NN + SCAN_CHUNK - 1) / SCAN_CHUNK)   // 13

// ---------------- scratch (static device globals; no allocation) ------------
__device__ float  g_x[(size_t)NN * HID];
__device__ __align__(16) __half g_xwh[(size_t)NN * HID];
__device__ float  g_dis[NN];
__device__ __align__(16) int g_cnt[NN];
__device__ int    g_rowptr[NN + 1];
__device__ __align__(16) int g_pos[NN];
__device__ __align__(16) int g_col[EE];
__device__ int    g_bsum[NSCAN];
__device__ int    g_boff[NSCAN];
__device__ __align__(16) uint g_WpF[PROJ_FRAG_WORDS];
__device__ __align__(16) uint g_WgF[2][GCN_FRAG_WORDS];

__device__ __forceinline__ uint f2tf32(float x) {
    uint r;
    asm("cvt.rna.tf32.f32 %0, %1;" : "=r"(r) : "f"(x));
    return r;
}
__device__ __forceinline__ float4 h8_to_f4(uint a, uint b) {
    __half2 ha = *(__half2*)&a, hb = *(__half2*)&b;
    float2 fa = __half22float2(ha), fb = __half22float2(hb);
    return make_float4(fa.x, fa.y, fb.x, fb.y);
}

// R11 fragment layout: word = ((ntile*4 + k8)*64) + lane*2 + jj
__device__ __forceinline__ void frag_coords(int word, int& k_off, int& n) {
    int blk = word >> 6, rem = word & 63;
    int ntile = blk >> 2, k8 = blk & 3;
    int lane = rem >> 1, jj = rem & 1;
    k_off = k8 * 8 + jj * 4 + (lane & 3);
    n = ntile * 8 + (lane >> 2);
}

// ---------------- prep: proj fragments (main stream) ------------------------
__global__ void prep_proj_k(const float* __restrict__ pW) {
    int i = blockIdx.x * blockDim.x + threadIdx.x;
    if (i < PROJ_FRAG_WORDS) {
        int it = i >> 12, word = i & 4095;
        int ko, n;
        frag_coords(word, ko, n);
        int k = it * 32 + ko;
        float v = (n < PO) ? pW[k * PO + n] : 0.0f;
        g_WpF[i] = f2tf32(v);
    }
}

// ---------------- prep: gcn fragments (side stream) -------------------------
__global__ void prep_gcn_k(const float* __restrict__ gW) {
    int i = blockIdx.x * blockDim.x + threadIdx.x;
    if (i < 2 * GCN_FRAG_WORDS) {
        int layer = i >> 14;
        int w = i & (GCN_FRAG_WORDS - 1);
        int it = w >> 12, word = w & 4095;
        int ko, n;
        frag_coords(word, ko, n);
        int k = it * 32 + ko;
        g_WgF[layer][w] = f2tf32(gW[(size_t)layer * HID * HID + k * HID + n]);
    }
}

// ---------------- zero counters (side stream) -------------------------------
__global__ void zero_cnt_k() {
    int i = blockIdx.x * blockDim.x + threadIdx.x;
    if (i < NN) g_cnt[i] = 0;
}

// ---------------- CSR build (side stream) -----------------------------------
__global__ void count_k(const int* __restrict__ dst) {
    int e0 = (blockIdx.x * blockDim.x + threadIdx.x) * 4;
    if (e0 < EE) {
        int4 d = *(const int4*)(dst + e0);
        atomicAdd(&g_cnt[d.x], 1);
        atomicAdd(&g_cnt[d.y], 1);
        atomicAdd(&g_cnt[d.z], 1);
        atomicAdd(&g_cnt[d.w], 1);
    }
}

// ---- parallel scan, 3 phases (13 blocks / 1 warp / 13 blocks) --------------
// scan1: block-local inclusive scan of 4096-elem chunk; element-incl -> g_pos
//        (temp), block total -> g_bsum.
__global__ void scan1_k() {
    __shared__ int warp_tot[32];
    int tid = threadIdx.x, lane = tid & 31, w = tid >> 5;
    int i0 = blockIdx.x * SCAN_CHUNK + tid * 4;
    int4 v = make_int4(0, 0, 0, 0);
    if (i0 < NN) v = *(const int4*)(g_cnt + i0);
    int s = v.x + v.y + v.z + v.w;
    int x = s;
    #pragma unroll
    for (int o = 1; o < 32; o <<= 1) {
        int y = __shfl_up_sync(0xffffffffu, x, o);
        if (lane >= o) x += y;
    }
    if (lane == 31) warp_tot[w] = x;
    __syncthreads();
    if (w == 0) {
        int t = warp_tot[lane];
        #pragma unroll
        for (int o = 1; o < 32; o <<= 1) {
            int y = __shfl_up_sync(0xffffffffu, t, o);
            if (lane >= o) t += y;
        }
        warp_tot[lane] = t;
    }
    __syncthreads();
    int woff = (w > 0) ? warp_tot[w - 1] : 0;
    int incl = x + woff;
    int excl = incl - s;
    if (i0 < NN) {
        int4 li;
        li.x = excl + v.x;
        li.y = li.x + v.y;
        li.z = li.y + v.z;
        li.w = li.z + v.w;
        *(int4*)(g_pos + i0) = li;       // temp: local inclusive
    }
    if (tid == 1023) g_bsum[blockIdx.x] = incl;
}

// scan2: one warp scans the 13 block totals -> exclusive offsets
__global__ void scan2_k() {
    int lane = threadIdx.x;
    int v = (lane < NSCAN) ? g_bsum[lane] : 0;
    int x = v;
    #pragma unroll
    for (int o = 1; o < 32; o <<= 1) {
        int y = __shfl_up_sync(0xffffffffu, x, o);
        if (lane >= o) x += y;
    }
    if (lane < NSCAN) g_boff[lane] = x - v;
    if (lane == 0) g_rowptr[0] = 0;
}

// scan3: add block offset; emit rowptr, pos (exclusive), dis
__global__ void scan3_k() {
    int tid = threadIdx.x;
    int i0 = blockIdx.x * SCAN_CHUNK + tid * 4;
    if (i0 >= NN) return;
    int off = g_boff[blockIdx.x];
    int4 v  = *(const int4*)(g_cnt + i0);
    int4 li = *(const int4*)(g_pos + i0);
    int4 incl = make_int4(li.x + off, li.y + off, li.z + off, li.w + off);
    g_rowptr[i0 + 1] = incl.x;
    g_rowptr[i0 + 2] = incl.y;
    g_rowptr[i0 + 3] = incl.z;
    g_rowptr[i0 + 4] = incl.w;
    *(int4*)(g_pos + i0) = make_int4(incl.x - v.x, incl.y - v.y,
                                     incl.z - v.z, incl.w - v.w);
    g_dis[i0 + 0] = rsqrtf(1.0f + (float)v.x);
    g_dis[i0 + 1] = rsqrtf(1.0f + (float)v.y);
    g_dis[i0 + 2] = rsqrtf(1.0f + (float)v.z);
    g_dis[i0 + 3] = rsqrtf(1.0f + (float)v.w);
}

__global__ void fill_k(const int* __restrict__ src, const int* __restrict__ dst) {
    int e0 = (blockIdx.x * blockDim.x + threadIdx.x) * 4;
    if (e0 < EE) {
        int4 d = *(const int4*)(dst + e0);
        int4 s = *(const int4*)(src + e0);
        int p0 = atomicAdd(&g_pos[d.x], 1);
        int p1 = atomicAdd(&g_pos[d.y], 1);
        int p2 = atomicAdd(&g_pos[d.z], 1);
        int p3 = atomicAdd(&g_pos[d.w], 1);
        g_col[p0] = s.x; g_col[p1] = s.y; g_col[p2] = s.z; g_col[p3] = s.w;
    }
}

// ---------------- tf32 mma GEMM, double-buffered, cp.async B (R11) ----------
#define BSA 132
#define ASZ (32 * BSA)
#define BSZ 4096

template<int K, int LDA, bool PROJ>
__global__ __launch_bounds__(256, 2) void mma_gemm_k(const float* __restrict__ A,
                                                     const uint* __restrict__ WF,
                                                     const float* __restrict__ bias,
                                                     const int* __restrict__ ids,
                                                     const float* __restrict__ emb,
                                                     float* __restrict__ outf,
                                                     __half* __restrict__ outh) {
    __shared__ __align__(16) uint As[2][ASZ];
    __shared__ __align__(16) uint Bs[2][BSZ];
    int tid = threadIdx.x;
    int lane = tid & 31, wid = tid >> 5;
    int warp_m = wid >> 2;
    int warp_n = wid & 3;
    int row0 = blockIdx.x * 128;
    const int NT = K / 32;

    float acc[4][4][4];
    #pragma unroll
    for (int mt = 0; mt < 4; mt++)
        #pragma unroll
        for (int nt = 0; nt < 4; nt++)
            #pragma unroll
            for (int j = 0; j < 4; j++) acc[mt][nt][j] = 0.0f;

    float4 va[4];

    auto loadA = [&](int k0) {
        #pragma unroll
        for (int i = 0; i < 4; i++) {
            int f = tid + i * 256;
            int r = f >> 3, c = (f & 7) * 4;
            int gr = row0 + r;
            va[i] = make_float4(0.f, 0.f, 0.f, 0.f);
            if (gr < NN) va[i] = *(const float4*)(A + (size_t)gr * LDA + k0 + c);
        }
    };
    auto storeA = [&](int buf) {
        #pragma unroll
        for (int i = 0; i < 4; i++) {
            int f = tid + i * 256;
            int r = f >> 3, c = (f & 7) * 4;
            int mtile = r >> 4, rloc = r & 15;
            int j = (rloc >> 3) + 2 * ((c >> 2) & 1);
            int tb = (rloc & 7) * 4;
            uint* dst = As[buf] + ((mtile << 2) + (c >> 3)) * BSA + j;
            dst[(tb + 0) * 4] = __float_as_uint(va[i].x);
            dst[(tb + 1) * 4] = __float_as_uint(va[i].y);
            dst[(tb + 2) * 4] = __float_as_uint(va[i].z);
            dst[(tb + 3) * 4] = __float_as_uint(va[i].w);
        }
    };
    auto stageB = [&](int it, int buf) {
        const uint* src = WF + (size_t)it * ITER_WORDS + tid * 16;
        uint sm = (uint)__cvta_generic_to_shared(Bs[buf] + tid * 16);
        #pragma unroll
        for (int i = 0; i < 4; i++)
            asm volatile("cp.async.ca.shared.global [%0], [%1], 16;"
                         :: "r"(sm + i * 16), "l"(src + i * 4));
        asm volatile("cp.async.commit_group;");
    };

    loadA(0);
    stageB(0, 0);
    storeA(0);
    asm volatile("cp.async.wait_group 0;" ::: "memory");
    __syncthreads();

    for (int it = 0; it < NT; it++) {
        int cur = it & 1;
        if (it + 1 < NT) {
            stageB(it + 1, cur ^ 1);
            loadA((it + 1) * 32);
        }

        #pragma unroll
        for (int k8 = 0; k8 < 4; k8++) {
            uint4 a[4];
            uint2 b[4];
            #pragma unroll
            for (int mt = 0; mt < 4; mt++)
                a[mt] = *(const uint4*)(As[cur] + (((warp_m * 4 + mt) << 2) + k8) * BSA + lane * 4);
            #pragma unroll
            for (int nt = 0; nt < 4; nt++)
                b[nt] = *(const uint2*)(Bs[cur] + (((warp_n * 4 + nt) << 2) + k8) * 64 + lane * 2);
            #pragma unroll
            for (int mt = 0; mt < 4; mt++)
                #pragma unroll
                for (int nt = 0; nt < 4; nt++) {
                    asm volatile(
                        "mma.sync.aligned.m16n8k8.row.col.f32.tf32.tf32.f32 "
                        "{%0,%1,%2,%3}, {%4,%5,%6,%7}, {%8,%9}, {%0,%1,%2,%3};"
                        : "+f"(acc[mt][nt][0]), "+f"(acc[mt][nt][1]),
                          "+f"(acc[mt][nt][2]), "+f"(acc[mt][nt][3])
                        : "r"(a[mt].x), "r"(a[mt].y), "r"(a[mt].z), "r"(a[mt].w),
                          "r"(b[nt].x), "r"(b[nt].y));
                }
        }

        if (it + 1 < NT) {
            storeA(cur ^ 1);
            asm volatile("cp.async.wait_group 0;" ::: "memory");
            __syncthreads();
        }
    }

    #pragma unroll
    for (int mt = 0; mt < 4; mt++) {
        int gr0 = row0 + warp_m * 64 + mt * 16 + (lane >> 2);
        int gr1 = gr0 + 8;
        float s0 = 1.f, s1 = 1.f;
        if (!PROJ) {
            if (gr0 < NN) s0 = g_dis[gr0];
            if (gr1 < NN) s1 = g_dis[gr1];
        }
        #pragma unroll
        for (int nt = 0; nt < 4; nt++) {
            int col = warp_n * 32 + nt * 8 + (lane & 3) * 2;
            if (PROJ) {
                if (col < PO) {
                    float b0 = bias[col], b1 = bias[col + 1];
                    if (gr0 < NN)
                        *(float2*)(outf + (size_t)gr0 * 128 + col) =
                            make_float2(acc[mt][nt][0] + b0, acc[mt][nt][1] + b1);
                    if (gr1 < NN)
                        *(float2*)(outf + (size_t)gr1 * 128 + col) =
                            make_float2(acc[mt][nt][2] + b0, acc[mt][nt][3] + b1);
                } else {
                    int t = col - PO;
                    if (gr0 < NN) {
                        float2 ev = *(const float2*)(emb + ids[gr0] * SD + t);
                        *(float2*)(outf + (size_t)gr0 * 128 + col) = ev;
                    }
                    if (gr1 < NN) {
                        float2 ev = *(const float2*)(emb + ids[gr1] * SD + t);
                        *(float2*)(outf + (size_t)gr1 * 128 + col) = ev;
                    }
                }
            } else {
                if (gr0 < NN)
                    *(__half2*)(outh + (size_t)gr0 * 128 + col) =
                        __floats2half2_rn(acc[mt][nt][0] * s0, acc[mt][nt][1] * s0);
                if (gr1 < NN)
                    *(__half2*)(outh + (size_t)gr1 * 128 + col) =
                        __floats2half2_rn(acc[mt][nt][2] * s1, acc[mt][nt][3] * s1);
            }
        }
    }
}

// ---------------- aggregation: half-warp per row (2 rows/warp) --------------
template<bool LAST>
__global__ void agg_k(const float* __restrict__ bias,
                      const float* __restrict__ lng,
                      const float* __restrict__ lnb,
                      float* __restrict__ out) {
    int warp = threadIdx.x >> 5, lane = threadIdx.x & 31;
    int half = lane >> 4, hl = lane & 15;
    int row = blockIdx.x * 16 + warp * 2 + half;
    if (row >= NN) return;
    const uint4* xw4 = (const uint4*)g_xwh;
    size_t rb = (size_t)row * 16 + hl;
    uint4 ps = xw4[rb];
    float4 a0 = h8_to_f4(ps.x, ps.y);
    float4 a1 = h8_to_f4(ps.z, ps.w);
    int e = g_rowptr[row], end = g_rowptr[row + 1];
    for (; e + 8 <= end; e += 8) {
        int s0 = g_col[e],     s1 = g_col[e + 1], s2 = g_col[e + 2], s3 = g_col[e + 3];
        int s4 = g_col[e + 4], s5 = g_col[e + 5], s6 = g_col[e + 6], s7 = g_col[e + 7];
        uint4 q0 = xw4[(size_t)s0 * 16 + hl];
        uint4 q1 = xw4[(size_t)s1 * 16 + hl];
        uint4 q2 = xw4[(size_t)s2 * 16 + hl];
        uint4 q3 = xw4[(size_t)s3 * 16 + hl];
        uint4 q4 = xw4[(size_t)s4 * 16 + hl];
        uint4 q5 = xw4[(size_t)s5 * 16 + hl];
        uint4 q6 = xw4[(size_t)s6 * 16 + hl];
        uint4 q7 = xw4[(size_t)s7 * 16 + hl];
        float4 u;
        u = h8_to_f4(q0.x, q0.y); a0.x += u.x; a0.y += u.y; a0.z += u.z; a0.w += u.w;
        u = h8_to_f4(q0.z, q0.w); a1.x += u.x; a1.y += u.y; a1.z += u.z; a1.w += u.w;
        u = h8_to_f4(q1.x, q1.y); a0.x += u.x; a0.y += u.y; a0.z += u.z; a0.w += u.w;
        u = h8_to_f4(q1.z, q1.w); a1.x += u.x; a1.y += u.y; a1.z += u.z; a1.w += u.w;
        u = h8_to_f4(q2.x, q2.y); a0.x += u.x; a0.y += u.y; a0.z += u.z; a0.w += u.w;
        u = h8_to_f4(q2.z, q2.w); a1.x += u.x; a1.y += u.y; a1.z += u.z; a1.w += u.w;
        u = h8_to_f4(q3.x, q3.y); a0.x += u.x; a0.y += u.y; a0.z += u.z; a0.w += u.w;
        u = h8_to_f4(q3.z, q3.w); a1.x += u.x; a1.y += u.y; a1.z += u.z; a1.w += u.w;
        u = h8_to_f4(q4.x, q4.y); a0.x += u.x; a0.y += u.y; a0.z += u.z; a0.w += u.w;
        u = h8_to_f4(q4.z, q4.w); a1.x += u.x; a1.y += u.y; a1.z += u.z; a1.w += u.w;
        u = h8_to_f4(q5.x, q5.y); a0.x += u.x; a0.y += u.y; a0.z += u.z; a0.w += u.w;
        u = h8_to_f4(q5.z, q5.w); a1.x += u.x; a1.y += u.y; a1.z += u.z; a1.w += u.w;
        u = h8_to_f4(q6.x, q6.y); a0.x += u.x; a0.y += u.y; a0.z += u.z; a0.w += u.w;
        u = h8_to_f4(q6.z, q6.w); a1.x += u.x; a1.y += u.y; a1.z += u.z; a1.w += u.w;
        u = h8_to_f4(q7.x, q7.y); a0.x += u.x; a0.y += u.y; a0.z += u.z; a0.w += u.w;
        u = h8_to_f4(q7.z, q7.w); a1.x += u.x; a1.y += u.y; a1.z += u.z; a1.w += u.w;
    }
    for (; e + 4 <= end; e += 4) {
        int s0 = g_col[e], s1 = g_col[e + 1], s2 = g_col[e + 2], s3 = g_col[e + 3];
        uint4 q0 = xw4[(size_t)s0 * 16 + hl];
        uint4 q1 = xw4[(size_t)s1 * 16 + hl];
        uint4 q2 = xw4[(size_t)s2 * 16 + hl];
        uint4 q3 = xw4[(size_t)s3 * 16 + hl];
        float4 u;
        u = h8_to_f4(q0.x, q0.y); a0.x += u.x; a0.y += u.y; a0.z += u.z; a0.w += u.w;
        u = h8_to_f4(q0.z, q0.w); a1.x += u.x; a1.y += u.y; a1.z += u.z; a1.w += u.w;
        u = h8_to_f4(q1.x, q1.y); a0.x += u.x; a0.y += u.y; a0.z += u.z; a0.w += u.w;
        u = h8_to_f4(q1.z, q1.w); a1.x += u.x; a1.y += u.y; a1.z += u.z; a1.w += u.w;
        u = h8_to_f4(q2.x, q2.y); a0.x += u.x; a0.y += u.y; a0.z += u.z; a0.w += u.w;
        u = h8_to_f4(q2.z, q2.w); a1.x += u.x; a1.y += u.y; a1.z += u.z; a1.w += u.w;
        u = h8_to_f4(q3.x, q3.y); a0.x += u.x; a0.y += u.y; a0.z += u.z; a0.w += u.w;
        u = h8_to_f4(q3.z, q3.w); a1.x += u.x; a1.y += u.y; a1.z += u.z; a1.w += u.w;
    }
    for (; e < end; e++) {
        uint4 q = xw4[(size_t)g_col[e] * 16 + hl];
        float4 u;
        u = h8_to_f4(q.x, q.y); a0.x += u.x; a0.y += u.y; a0.z += u.z; a0.w += u.w;
        u = h8_to_f4(q.z, q.w); a1.x += u.x; a1.y += u.y; a1.z += u.z; a1.w += u.w;
    }
    float d = g_dis[row];
    const float4* b4 = (const float4*)bias;
    float4 bb0 = b4[hl * 2], bb1 = b4[hl * 2 + 1];
    const float4* x4 = (const float4*)g_x;
    float4 x0 = x4[(size_t)row * 32 + hl * 2];
    float4 x1 = x4[(size_t)row * 32 + hl * 2 + 1];
    float4 v0, v1;
    v0.x = x0.x + fmaxf(d * a0.x + bb0.x, 0.f);
    v0.y = x0.y + fmaxf(d * a0.y + bb0.y, 0.f);
    v0.z = x0.z + fmaxf(d * a0.z + bb0.z, 0.f);
    v0.w = x0.w + fmaxf(d * a0.w + bb0.w, 0.f);
    v1.x = x1.x + fmaxf(d * a1.x + bb1.x, 0.f);
    v1.y = x1.y + fmaxf(d * a1.y + bb1.y, 0.f);
    v1.z = x1.z + fmaxf(d * a1.z + bb1.z, 0.f);
    v1.w = x1.w + fmaxf(d * a1.w + bb1.w, 0.f);
    if (!LAST) {
        ((float4*)g_x)[(size_t)row * 32 + hl * 2] = v0;
        ((float4*)g_x)[(size_t)row * 32 + hl * 2 + 1] = v1;
    } else {
        float s  = (v0.x + v0.y + v0.z + v0.w) + (v1.x + v1.y + v1.z + v1.w);
        float s2 = (v0.x * v0.x + v0.y * v0.y + v0.z * v0.z + v0.w * v0.w)
                 + (v1.x * v1.x + v1.y * v1.y + v1.z * v1.z + v1.w * v1.w);
        #pragma unroll
        for (int o = 8; o; o >>= 1) {
            s  += __shfl_xor_sync(0xffffffffu, s, o);
            s2 += __shfl_xor_sync(0xffffffffu, s2, o);
        }
        float mean = s * (1.0f / 128.0f);
        float var = s2 * (1.0f / 128.0f) - mean * mean;
        float rstd = rsqrtf(var + 1e-5f);
        const float4* g4 = (const float4*)lng;
        const float4* lb4 = (const float4*)lnb;
        float4 gg0 = g4[hl * 2], gg1 = g4[hl * 2 + 1];
        float4 lb0 = lb4[hl * 2], lb1 = lb4[hl * 2 + 1];
        float4 o0, o1;
        o0.x = (v0.x - mean) * rstd * gg0.x + lb0.x;
        o0.y = (v0.y - mean) * rstd * gg0.y + lb0.y;
        o0.z = (v0.z - mean) * rstd * gg0.z + lb0.z;
        o0.w = (v0.w - mean) * rstd * gg0.w + lb0.w;
        o1.x = (v1.x - mean) * rstd * gg1.x + lb1.x;
        o1.y = (v1.y - mean) * rstd * gg1.y + lb1.y;
        o1.z = (v1.z - mean) * rstd * gg1.z + lb1.z;
        o1.w = (v1.w - mean) * rstd * gg1.w + lb1.w;
        ((float4*)out)[(size_t)row * 32 + hl * 2] = o0;
        ((float4*)out)[(size_t)row * 32 + hl * 2 + 1] = o1;
    }
}

// ---------------- launcher --------------------------------------------------
static cudaStream_t g_s1 = nullptr;
static cudaEvent_t  g_evFork = nullptr, g_evScan = nullptr, g_evFill = nullptr;

extern "C" void kernel_launch(void* const* d_in, const int* in_sizes, int n_in,
                              void* d_out, int out_size) {
    const float* llm = (const float*)d_in[0];
    const int*   ids = (const int*)d_in[1];
    const int*   ei  = (const int*)d_in[2];
    const float* pW  = (const float*)d_in[3];
    const float* pb  = (const float*)d_in[4];
    const float* emb = (const float*)d_in[5];
    const float* gW  = (const float*)d_in[6];
    const float* gb  = (const float*)d_in[7];
    const float* lg  = (const float*)d_in[8];
    const float* lb  = (const float*)d_in[9];
    const int* src = ei;
    const int* dst = ei + EE;

    const int MB = (NN + 127) / 128;
    const int HB = (NN + 15) / 16;
    const int EB4 = (EE / 4 + 255) / 256;

    if (g_s1 == nullptr) {
        cudaStreamCreateWithFlags(&g_s1, cudaStreamNonBlocking);
        cudaEventCreateWithFlags(&g_evFork, cudaEventDisableTiming);
        cudaEventCreateWithFlags(&g_evScan, cudaEventDisableTiming);
        cudaEventCreateWithFlags(&g_evFill, cudaEventDisableTiming);
    }

    float*  d_x  = nullptr; cudaGetSymbolAddress((void**)&d_x,  g_x);
    __half* d_xw = nullptr; cudaGetSymbolAddress((void**)&d_xw, g_xwh);
    uint*   d_WpF = nullptr; cudaGetSymbolAddress((void**)&d_WpF, g_WpF);
    uint*   d_WgF = nullptr; cudaGetSymbolAddress((void**)&d_WgF, g_WgF);

    // ---- fork: GCN frag prep + CSR chain on side stream ----
    cudaEventRecord(g_evFork, 0);
    cudaStreamWaitEvent(g_s1, g_evFork, 0);

    prep_gcn_k<<<(2 * GCN_FRAG_WORDS + 255) / 256, 256, 0, g_s1>>>(gW);
    zero_cnt_k<<<(NN + 255) / 256, 256, 0, g_s1>>>();
    count_k<<<EB4, 256, 0, g_s1>>>(dst);
    scan1_k<<<NSCAN, 1024, 0, g_s1>>>();
    scan2_k<<<1, 32, 0, g_s1>>>();
    scan3_k<<<NSCAN, 1024, 0, g_s1>>>();
    cudaEventRecord(g_evScan, g_s1);   // covers prep_gcn + dis
    fill_k<<<EB4, 256, 0, g_s1>>>(src, dst);
    cudaEventRecord(g_evFill, g_s1);

    // ---- main stream: proj frag prep + proj ----
    prep_proj_k<<<(PROJ_FRAG_WORDS + 255) / 256, 256>>>(pW);
    mma_gemm_k<LLM, LLM, true><<<MB, 256>>>(llm, d_WpF, pb, ids, emb, d_x, nullptr);

    cudaStreamWaitEvent(0, g_evScan, 0);
    mma_gemm_k<HID, HID, false><<<MB, 256>>>(d_x, d_WgF, nullptr, nullptr, nullptr,
                                             nullptr, d_xw);
    cudaStreamWaitEvent(0, g_evFill, 0);
    agg_k<false><<<HB, 256>>>(gb, nullptr, nullptr, nullptr);

    mma_gemm_k<HID, HID, false><<<MB, 256>>>(d_x, d_WgF + GCN_FRAG_WORDS, nullptr,
                                             nullptr, nullptr, nullptr, d_xw);
    agg_k<true><<<HB, 256>>>(gb + HID, lg, lb, (float*)d_out);
}

// round 14
// speedup vs baseline: 1.1769x; 1.0422x over previous
#include <cuda_runtime.h>
#include <cuda_fp16.h>

#define NN 50000
#define NNPAD 50048
#define EE 600000
#define LLM 640
#define HID 128
#define PO 112
#define SD 16

typedef unsigned int uint;

#define PROJ_ITS 20
#define ITER_WORDS 4096
#define PROJ_FRAG_WORDS (PROJ_ITS * ITER_WORDS)
#define GCNH_WORDS 8192          // fp16 B image words per layer (4 iters * 2048)

#define SCAN_CHUNK 4096
#define NSCAN ((NN + SCAN_CHUNK - 1) / SCAN_CHUNK)   // 13

// ---------------- scratch (static device globals; no allocation) ------------
__device__ float  g_x[(size_t)NN * HID];
__device__ __align__(16) __half g_xh[(size_t)NNPAD * HID];   // fp16 mirror of x
__device__ __align__(16) __half g_xwh[(size_t)NN * HID];     // xws fp16
__device__ float  g_dis[NN];
__device__ __align__(16) int g_cnt[NN];
__device__ int    g_rowptr[NN + 1];
__device__ __align__(16) int g_pos[NN];
__device__ __align__(16) int g_col[EE];
__device__ int    g_bsum[NSCAN];
__device__ int    g_boff[NSCAN];
__device__ __align__(16) uint g_WpF[PROJ_FRAG_WORDS];        // proj B tf32 frags
__device__ __align__(16) uint g_WgH[2][GCNH_WORDS];          // gcn B fp16 frags

__device__ __forceinline__ uint f2tf32(float x) {
    uint r;
    asm("cvt.rna.tf32.f32 %0, %1;" : "=r"(r) : "f"(x));
    return r;
}
__device__ __forceinline__ float4 h8_to_f4(uint a, uint b) {
    __half2 ha = *(__half2*)&a, hb = *(__half2*)&b;
    float2 fa = __half22float2(ha), fb = __half22float2(hb);
    return make_float4(fa.x, fa.y, fb.x, fb.y);
}

// proj fragment layout (R11): word = ((ntile*4 + k8)*64) + lane*2 + jj
__global__ void prep_proj_k(const float* __restrict__ pW) {
    int i = blockIdx.x * blockDim.x + threadIdx.x;
    if (i < PROJ_FRAG_WORDS) {
        int it = i >> 12, word = i & 4095;
        int blk = word >> 6, rem = word & 63;
        int ntile = blk >> 2, k8 = blk & 3;
        int lane = rem >> 1, jj = rem & 1;
        int k = it * 32 + k8 * 8 + jj * 4 + (lane & 3);
        int n = ntile * 8 + (lane >> 2);
        float v = (n < PO) ? pW[k * PO + n] : 0.0f;
        g_WpF[i] = f2tf32(v);
    }
}

// gcn fp16 B image + zero counters (side stream).
// word w (per layer): it = w>>11; word2048 = w&2047; blk = word2048>>6 (nt*2+s);
// rem = word2048&63: lane = rem>>1, j = rem&1.
// k = it*32 + s*16 + (lane&3)*2 + j*8 ; n = nt*8 + (lane>>2); half2(W[k][n], W[k+1][n])
__global__ void prep_gcn_k(const float* __restrict__ gW) {
    int i = blockIdx.x * blockDim.x + threadIdx.x;
    if (i < NN) g_cnt[i] = 0;
    if (i < 2 * GCNH_WORDS) {
        int layer = i >> 13;
        int w = i & (GCNH_WORDS - 1);
        int it = w >> 11, word = w & 2047;
        int blk = word >> 6, rem = word & 63;
        int nt = blk >> 1, s = blk & 1;
        int lane = rem >> 1, j = rem & 1;
        int k = it * 32 + s * 16 + (lane & 3) * 2 + j * 8;
        int n = nt * 8 + (lane >> 2);
        const float* Wl = gW + (size_t)layer * HID * HID;
        __half2 h = __floats2half2_rn(Wl[k * HID + n], Wl[(k + 1) * HID + n]);
        g_WgH[layer][w] = *(uint*)&h;
    }
}

// ---------------- CSR build (side stream) -----------------------------------
__global__ void count_k(const int* __restrict__ dst) {
    int e0 = (blockIdx.x * blockDim.x + threadIdx.x) * 4;
    if (e0 < EE) {
        int4 d = *(const int4*)(dst + e0);
        atomicAdd(&g_cnt[d.x], 1);
        atomicAdd(&g_cnt[d.y], 1);
        atomicAdd(&g_cnt[d.z], 1);
        atomicAdd(&g_cnt[d.w], 1);
    }
}

__global__ void scan1_k() {
    __shared__ int warp_tot[32];
    int tid = threadIdx.x, lane = tid & 31, w = tid >> 5;
    int i0 = blockIdx.x * SCAN_CHUNK + tid * 4;
    int4 v = make_int4(0, 0, 0, 0);
    if (i0 < NN) v = *(const int4*)(g_cnt + i0);
    int s = v.x + v.y + v.z + v.w;
    int x = s;
    #pragma unroll
    for (int o = 1; o < 32; o <<= 1) {
        int y = __shfl_up_sync(0xffffffffu, x, o);
        if (lane >= o) x += y;
    }
    if (lane == 31) warp_tot[w] = x;
    __syncthreads();
    if (w == 0) {
        int t = warp_tot[lane];
        #pragma unroll
        for (int o = 1; o < 32; o <<= 1) {
            int y = __shfl_up_sync(0xffffffffu, t, o);
            if (lane >= o) t += y;
        }
        warp_tot[lane] = t;
    }
    __syncthreads();
    int woff = (w > 0) ? warp_tot[w - 1] : 0;
    int incl = x + woff;
    int excl = incl - s;
    if (i0 < NN) {
        int4 li;
        li.x = excl + v.x;
        li.y = li.x + v.y;
        li.z = li.y + v.z;
        li.w = li.z + v.w;
        *(int4*)(g_pos + i0) = li;
    }
    if (tid == 1023) g_bsum[blockIdx.x] = incl;
}

__global__ void scan2_k() {
    int lane = threadIdx.x;
    int v = (lane < NSCAN) ? g_bsum[lane] : 0;
    int x = v;
    #pragma unroll
    for (int o = 1; o < 32; o <<= 1) {
        int y = __shfl_up_sync(0xffffffffu, x, o);
        if (lane >= o) x += y;
    }
    if (lane < NSCAN) g_boff[lane] = x - v;
    if (lane == 0) g_rowptr[0] = 0;
}

__global__ void scan3_k() {
    int tid = threadIdx.x;
    int i0 = blockIdx.x * SCAN_CHUNK + tid * 4;
    if (i0 >= NN) return;
    int off = g_boff[blockIdx.x];
    int4 v  = *(const int4*)(g_cnt + i0);
    int4 li = *(const int4*)(g_pos + i0);
    int4 incl = make_int4(li.x + off, li.y + off, li.z + off, li.w + off);
    g_rowptr[i0 + 1] = incl.x;
    g_rowptr[i0 + 2] = incl.y;
    g_rowptr[i0 + 3] = incl.z;
    g_rowptr[i0 + 4] = incl.w;
    *(int4*)(g_pos + i0) = make_int4(incl.x - v.x, incl.y - v.y,
                                     incl.z - v.z, incl.w - v.w);
    g_dis[i0 + 0] = rsqrtf(1.0f + (float)v.x);
    g_dis[i0 + 1] = rsqrtf(1.0f + (float)v.y);
    g_dis[i0 + 2] = rsqrtf(1.0f + (float)v.z);
    g_dis[i0 + 3] = rsqrtf(1.0f + (float)v.w);
}

__global__ void fill_k(const int* __restrict__ src, const int* __restrict__ dst) {
    int e0 = (blockIdx.x * blockDim.x + threadIdx.x) * 4;
    if (e0 < EE) {
        int4 d = *(const int4*)(dst + e0);
        int4 s = *(const int4*)(src + e0);
        int p0 = atomicAdd(&g_pos[d.x], 1);
        int p1 = atomicAdd(&g_pos[d.y], 1);
        int p2 = atomicAdd(&g_pos[d.z], 1);
        int p3 = atomicAdd(&g_pos[d.w], 1);
        g_col[p0] = s.x; g_col[p1] = s.y; g_col[p2] = s.z; g_col[p3] = s.w;
    }
}

// ---------------- proj GEMM: tf32 mma, double-buffered, cp.async B (R11) ----
#define BSA 132
#define ASZ (32 * BSA)
#define BSZ 4096

__global__ __launch_bounds__(256, 2) void proj_gemm_k(const float* __restrict__ A,
                                                      const uint* __restrict__ WF,
                                                      const float* __restrict__ bias,
                                                      const int* __restrict__ ids,
                                                      const float* __restrict__ emb) {
    __shared__ __align__(16) uint As[2][ASZ];
    __shared__ __align__(16) uint Bs[2][BSZ];
    int tid = threadIdx.x;
    int lane = tid & 31, wid = tid >> 5;
    int warp_m = wid >> 2;
    int warp_n = wid & 3;
    int row0 = blockIdx.x * 128;
    const int NT = LLM / 32;

    float acc[4][4][4];
    #pragma unroll
    for (int mt = 0; mt < 4; mt++)
        #pragma unroll
        for (int nt = 0; nt < 4; nt++)
            #pragma unroll
            for (int j = 0; j < 4; j++) acc[mt][nt][j] = 0.0f;

    float4 va[4];

    auto loadA = [&](int k0) {
        #pragma unroll
        for (int i = 0; i < 4; i++) {
            int f = tid + i * 256;
            int r = f >> 3, c = (f & 7) * 4;
            int gr = row0 + r;
            va[i] = make_float4(0.f, 0.f, 0.f, 0.f);
            if (gr < NN) va[i] = *(const float4*)(A + (size_t)gr * LLM + k0 + c);
        }
    };
    auto storeA = [&](int buf) {
        #pragma unroll
        for (int i = 0; i < 4; i++) {
            int f = tid + i * 256;
            int r = f >> 3, c = (f & 7) * 4;
            int mtile = r >> 4, rloc = r & 15;
            int j = (rloc >> 3) + 2 * ((c >> 2) & 1);
            int tb = (rloc & 7) * 4;
            uint* dst = As[buf] + ((mtile << 2) + (c >> 3)) * BSA + j;
            dst[(tb + 0) * 4] = __float_as_uint(va[i].x);
            dst[(tb + 1) * 4] = __float_as_uint(va[i].y);
            dst[(tb + 2) * 4] = __float_as_uint(va[i].z);
            dst[(tb + 3) * 4] = __float_as_uint(va[i].w);
        }
    };
    auto stageB = [&](int it, int buf) {
        const uint* src = WF + (size_t)it * ITER_WORDS + tid * 16;
        uint sm = (uint)__cvta_generic_to_shared(Bs[buf] + tid * 16);
        #pragma unroll
        for (int i = 0; i < 4; i++)
            asm volatile("cp.async.ca.shared.global [%0], [%1], 16;"
                         :: "r"(sm + i * 16), "l"(src + i * 4));
        asm volatile("cp.async.commit_group;");
    };

    loadA(0);
    stageB(0, 0);
    storeA(0);
    asm volatile("cp.async.wait_group 0;" ::: "memory");
    __syncthreads();

    for (int it = 0; it < NT; it++) {
        int cur = it & 1;
        if (it + 1 < NT) {
            stageB(it + 1, cur ^ 1);
            loadA((it + 1) * 32);
        }

        #pragma unroll
        for (int k8 = 0; k8 < 4; k8++) {
            uint4 a[4];
            uint2 b[4];
            #pragma unroll
            for (int mt = 0; mt < 4; mt++)
                a[mt] = *(const uint4*)(As[cur] + (((warp_m * 4 + mt) << 2) + k8) * BSA + lane * 4);
            #pragma unroll
            for (int nt = 0; nt < 4; nt++)
                b[nt] = *(const uint2*)(Bs[cur] + (((warp_n * 4 + nt) << 2) + k8) * 64 + lane * 2);
            #pragma unroll
            for (int mt = 0; mt < 4; mt++)
                #pragma unroll
                for (int nt = 0; nt < 4; nt++) {
                    asm volatile(
                        "mma.sync.aligned.m16n8k8.row.col.f32.tf32.tf32.f32 "
                        "{%0,%1,%2,%3}, {%4,%5,%6,%7}, {%8,%9}, {%0,%1,%2,%3};"
                        : "+f"(acc[mt][nt][0]), "+f"(acc[mt][nt][1]),
                          "+f"(acc[mt][nt][2]), "+f"(acc[mt][nt][3])
                        : "r"(a[mt].x), "r"(a[mt].y), "r"(a[mt].z), "r"(a[mt].w),
                          "r"(b[nt].x), "r"(b[nt].y));
                }
        }

        if (it + 1 < NT) {
            storeA(cur ^ 1);
            asm volatile("cp.async.wait_group 0;" ::: "memory");
            __syncthreads();
        }
    }

    // epilogue: fp32 x + fp16 mirror
    #pragma unroll
    for (int mt = 0; mt < 4; mt++) {
        int gr0 = row0 + warp_m * 64 + mt * 16 + (lane >> 2);
        int gr1 = gr0 + 8;
        #pragma unroll
        for (int nt = 0; nt < 4; nt++) {
            int col = warp_n * 32 + nt * 8 + (lane & 3) * 2;
            float2 v0, v1;
            if (col < PO) {
                float b0 = bias[col], b1 = bias[col + 1];
                v0 = make_float2(acc[mt][nt][0] + b0, acc[mt][nt][1] + b1);
                v1 = make_float2(acc[mt][nt][2] + b0, acc[mt][nt][3] + b1);
            } else {
                int t = col - PO;
                v0 = (gr0 < NN) ? *(const float2*)(emb + ids[gr0] * SD + t)
                                : make_float2(0.f, 0.f);
                v1 = (gr1 < NN) ? *(const float2*)(emb + ids[gr1] * SD + t)
                                : make_float2(0.f, 0.f);
            }
            if (gr0 < NN) {
                *(float2*)(g_x + (size_t)gr0 * 128 + col) = v0;
                *(__half2*)(g_xh + (size_t)gr0 * 128 + col) = __floats2half2_rn(v0.x, v0.y);
            }
            if (gr1 < NN) {
                *(float2*)(g_x + (size_t)gr1 * 128 + col) = v1;
                *(__half2*)(g_xh + (size_t)gr1 * 128 + col) = __floats2half2_rn(v1.x, v1.y);
            }
        }
    }
}

// ---------------- GCN GEMM: fp16 m16n8k16, A row-major smem, cp.async -------
// BM=128, BN=128, BK=32 (2 k16 steps/iter), NT=4. 8 warps (2m x 4n).
// A smem: row stride 36 words (32 data + 4 pad) -> conflict-free LDS.32 frags.
#define AROW 36
#define ASZH (128 * AROW)    // 4608 words (18 KB)
#define BSZH 2048            // words per iter image (8 KB)

__global__ __launch_bounds__(256, 2) void gcn_gemm_k(const uint* __restrict__ WF) {
    __shared__ __align__(16) uint As[2][ASZH];
    __shared__ __align__(16) uint Bs[2][BSZH];
    int tid = threadIdx.x;
    int lane = tid & 31, wid = tid >> 5;
    int warp_m = wid >> 2;
    int warp_n = wid & 3;
    int row0 = blockIdx.x * 128;

    float acc[4][4][4];
    #pragma unroll
    for (int mt = 0; mt < 4; mt++)
        #pragma unroll
        for (int nt = 0; nt < 4; nt++)
            #pragma unroll
            for (int j = 0; j < 4; j++) acc[mt][nt][j] = 0.0f;

    auto stageA = [&](int it, int buf) {   // 512 x 16B chunks, 2/thread
        #pragma unroll
        for (int i = 0; i < 2; i++) {
            int c = tid + i * 256;
            int r = c >> 2, q = c & 3;
            const __half* src = g_xh + (size_t)(row0 + r) * 128 + it * 32 + q * 8;
            uint sm = (uint)__cvta_generic_to_shared(As[buf] + r * AROW + q * 4);
            asm volatile("cp.async.ca.shared.global [%0], [%1], 16;"
                         :: "r"(sm), "l"(src));
        }
    };
    auto stageB = [&](int it, int buf) {   // 2048 words, 8/thread (2 x 16B)
        const uint* src = WF + it * BSZH + tid * 8;
        uint sm = (uint)__cvta_generic_to_shared(Bs[buf] + tid * 8);
        #pragma unroll
        for (int i = 0; i < 2; i++)
            asm volatile("cp.async.ca.shared.global [%0], [%1], 16;"
                         :: "r"(sm + i * 16), "l"(src + i * 4));
    };

    stageA(0, 0);
    stageB(0, 0);
    asm volatile("cp.async.commit_group;");
    asm volatile("cp.async.wait_group 0;" ::: "memory");
    __syncthreads();

    for (int it = 0; it < 4; it++) {
        int cur = it & 1;
        if (it + 1 < 4) {
            stageA(it + 1, cur ^ 1);
            stageB(it + 1, cur ^ 1);
            asm volatile("cp.async.commit_group;");
        }

        #pragma unroll
        for (int s = 0; s < 2; s++) {
            uint a[4][4];
            #pragma unroll
            for (int mt = 0; mt < 4; mt++) {
                int base = (warp_m * 64 + mt * 16 + (lane >> 2)) * AROW + s * 8 + (lane & 3);
                a[mt][0] = As[cur][base];                 // row r,   k..k+1
                a[mt][1] = As[cur][base + 8 * AROW];      // row r+8, k..k+1
                a[mt][2] = As[cur][base + 4];             // row r,   k+8..k+9
                a[mt][3] = As[cur][base + 8 * AROW + 4];  // row r+8, k+8..k+9
            }
            uint2 b[4];
            #pragma unroll
            for (int ntl = 0; ntl < 4; ntl++) {
                int nt = warp_n * 4 + ntl;
                b[ntl] = *(const uint2*)(Bs[cur] + (nt * 2 + s) * 64 + lane * 2);
            }
            #pragma unroll
            for (int mt = 0; mt < 4; mt++)
                #pragma unroll
                for (int ntl = 0; ntl < 4; ntl++) {
                    asm volatile(
                        "mma.sync.aligned.m16n8k16.row.col.f32.f16.f16.f32 "
                        "{%0,%1,%2,%3}, {%4,%5,%6,%7}, {%8,%9}, {%0,%1,%2,%3};"
                        : "+f"(acc[mt][ntl][0]), "+f"(acc[mt][ntl][1]),
                          "+f"(acc[mt][ntl][2]), "+f"(acc[mt][ntl][3])
                        : "r"(a[mt][0]), "r"(a[mt][1]), "r"(a[mt][2]), "r"(a[mt][3]),
                          "r"(b[ntl].x), "r"(b[ntl].y));
                }
        }

        if (it + 1 < 4) {
            asm volatile("cp.async.wait_group 0;" ::: "memory");
            __syncthreads();
        }
    }

    // epilogue: xws = dis * acc, fp16
    #pragma unroll
    for (int mt = 0; mt < 4; mt++) {
        int gr0 = row0 + warp_m * 64 + mt * 16 + (lane >> 2);
        int gr1 = gr0 + 8;
        float s0 = (gr0 < NN) ? g_dis[gr0] : 0.f;
        float s1 = (gr1 < NN) ? g_dis[gr1] : 0.f;
        #pragma unroll
        for (int nt = 0; nt < 4; nt++) {
            int col = warp_n * 32 + nt * 8 + (lane & 3) * 2;
            if (gr0 < NN)
                *(__half2*)(g_xwh + (size_t)gr0 * 128 + col) =
                    __floats2half2_rn(acc[mt][nt][0] * s0, acc[mt][nt][1] * s0);
            if (gr1 < NN)
                *(__half2*)(g_xwh + (size_t)gr1 * 128 + col) =
                    __floats2half2_rn(acc[mt][nt][2] * s1, acc[mt][nt][3] * s1);
        }
    }
}

// ---------------- aggregation: half-warp per row (2 rows/warp) --------------
template<bool LAST>
__global__ void agg_k(const float* __restrict__ bias,
                      const float* __restrict__ lng,
                      const float* __restrict__ lnb,
                      float* __restrict__ out) {
    int warp = threadIdx.x >> 5, lane = threadIdx.x & 31;
    int half = lane >> 4, hl = lane & 15;
    int row = blockIdx.x * 16 + warp * 2 + half;
    if (row >= NN) return;
    const uint4* xw4 = (const uint4*)g_xwh;
    uint4 ps = xw4[(size_t)row * 16 + hl];
    float4 a0 = h8_to_f4(ps.x, ps.y);
    float4 a1 = h8_to_f4(ps.z, ps.w);
    int e = g_rowptr[row], end = g_rowptr[row + 1];
    for (; e + 8 <= end; e += 8) {
        int s0 = g_col[e],     s1 = g_col[e + 1], s2 = g_col[e + 2], s3 = g_col[e + 3];
        int s4 = g_col[e + 4], s5 = g_col[e + 5], s6 = g_col[e + 6], s7 = g_col[e + 7];
        uint4 q0 = xw4[(size_t)s0 * 16 + hl];
        uint4 q1 = xw4[(size_t)s1 * 16 + hl];
        uint4 q2 = xw4[(size_t)s2 * 16 + hl];
        uint4 q3 = xw4[(size_t)s3 * 16 + hl];
        uint4 q4 = xw4[(size_t)s4 * 16 + hl];
        uint4 q5 = xw4[(size_t)s5 * 16 + hl];
        uint4 q6 = xw4[(size_t)s6 * 16 + hl];
        uint4 q7 = xw4[(size_t)s7 * 16 + hl];
        float4 u;
        u = h8_to_f4(q0.x, q0.y); a0.x += u.x; a0.y += u.y; a0.z += u.z; a0.w += u.w;
        u = h8_to_f4(q0.z, q0.w); a1.x += u.x; a1.y += u.y; a1.z += u.z; a1.w += u.w;
        u = h8_to_f4(q1.x, q1.y); a0.x += u.x; a0.y += u.y; a0.z += u.z; a0.w += u.w;
        u = h8_to_f4(q1.z, q1.w); a1.x += u.x; a1.y += u.y; a1.z += u.z; a1.w += u.w;
        u = h8_to_f4(q2.x, q2.y); a0.x += u.x; a0.y += u.y; a0.z += u.z; a0.w += u.w;
        u = h8_to_f4(q2.z, q2.w); a1.x += u.x; a1.y += u.y; a1.z += u.z; a1.w += u.w;
        u = h8_to_f4(q3.x, q3.y); a0.x += u.x; a0.y += u.y; a0.z += u.z; a0.w += u.w;
        u = h8_to_f4(q3.z, q3.w); a1.x += u.x; a1.y += u.y; a1.z += u.z; a1.w += u.w;
        u = h8_to_f4(q4.x, q4.y); a0.x += u.x; a0.y += u.y; a0.z += u.z; a0.w += u.w;
        u = h8_to_f4(q4.z, q4.w); a1.x += u.x; a1.y += u.y; a1.z += u.z; a1.w += u.w;
        u = h8_to_f4(q5.x, q5.y); a0.x += u.x; a0.y += u.y; a0.z += u.z; a0.w += u.w;
        u = h8_to_f4(q5.z, q5.w); a1.x += u.x; a1.y += u.y; a1.z += u.z; a1.w += u.w;
        u = h8_to_f4(q6.x, q6.y); a0.x += u.x; a0.y += u.y; a0.z += u.z; a0.w += u.w;
        u = h8_to_f4(q6.z, q6.w); a1.x += u.x; a1.y += u.y; a1.z += u.z; a1.w += u.w;
        u = h8_to_f4(q7.x, q7.y); a0.x += u.x; a0.y += u.y; a0.z += u.z; a0.w += u.w;
        u = h8_to_f4(q7.z, q7.w); a1.x += u.x; a1.y += u.y; a1.z += u.z; a1.w += u.w;
    }
    for (; e + 4 <= end; e += 4) {
        int s0 = g_col[e], s1 = g_col[e + 1], s2 = g_col[e + 2], s3 = g_col[e + 3];
        uint4 q0 = xw4[(size_t)s0 * 16 + hl];
        uint4 q1 = xw4[(size_t)s1 * 16 + hl];
        uint4 q2 = xw4[(size_t)s2 * 16 + hl];
        uint4 q3 = xw4[(size_t)s3 * 16 + hl];
        float4 u;
        u = h8_to_f4(q0.x, q0.y); a0.x += u.x; a0.y += u.y; a0.z += u.z; a0.w += u.w;
        u = h8_to_f4(q0.z, q0.w); a1.x += u.x; a1.y += u.y; a1.z += u.z; a1.w += u.w;
        u = h8_to_f4(q1.x, q1.y); a0.x += u.x; a0.y += u.y; a0.z += u.z; a0.w += u.w;
        u = h8_to_f4(q1.z, q1.w); a1.x += u.x; a1.y += u.y; a1.z += u.z; a1.w += u.w;
        u = h8_to_f4(q2.x, q2.y); a0.x += u.x; a0.y += u.y; a0.z += u.z; a0.w += u.w;
        u = h8_to_f4(q2.z, q2.w); a1.x += u.x; a1.y += u.y; a1.z += u.z; a1.w += u.w;
        u = h8_to_f4(q3.x, q3.y); a0.x += u.x; a0.y += u.y; a0.z += u.z; a0.w += u.w;
        u = h8_to_f4(q3.z, q3.w); a1.x += u.x; a1.y += u.y; a1.z += u.z; a1.w += u.w;
    }
    for (; e < end; e++) {
        uint4 q = xw4[(size_t)g_col[e] * 16 + hl];
        float4 u;
        u = h8_to_f4(q.x, q.y); a0.x += u.x; a0.y += u.y; a0.z += u.z; a0.w += u.w;
        u = h8_to_f4(q.z, q.w); a1.x += u.x; a1.y += u.y; a1.z += u.z; a1.w += u.w;
    }
    float d = g_dis[row];
    const float4* b4 = (const float4*)bias;
    float4 bb0 = b4[hl * 2], bb1 = b4[hl * 2 + 1];
    const float4* x4 = (const float4*)g_x;
    float4 x0 = x4[(size_t)row * 32 + hl * 2];
    float4 x1 = x4[(size_t)row * 32 + hl * 2 + 1];
    float4 v0, v1;
    v0.x = x0.x + fmaxf(d * a0.x + bb0.x, 0.f);
    v0.y = x0.y + fmaxf(d * a0.y + bb0.y, 0.f);
    v0.z = x0.z + fmaxf(d * a0.z + bb0.z, 0.f);
    v0.w = x0.w + fmaxf(d * a0.w + bb0.w, 0.f);
    v1.x = x1.x + fmaxf(d * a1.x + bb1.x, 0.f);
    v1.y = x1.y + fmaxf(d * a1.y + bb1.y, 0.f);
    v1.z = x1.z + fmaxf(d * a1.z + bb1.z, 0.f);
    v1.w = x1.w + fmaxf(d * a1.w + bb1.w, 0.f);
    if (!LAST) {
        ((float4*)g_x)[(size_t)row * 32 + hl * 2] = v0;
        ((float4*)g_x)[(size_t)row * 32 + hl * 2 + 1] = v1;
        // fp16 mirror for the next GCN GEMM's A
        uint4 hv;
        __half2 h0 = __floats2half2_rn(v0.x, v0.y);
        __half2 h1 = __floats2half2_rn(v0.z, v0.w);
        __half2 h2 = __floats2half2_rn(v1.x, v1.y);
        __half2 h3 = __floats2half2_rn(v1.z, v1.w);
        hv.x = *(uint*)&h0; hv.y = *(uint*)&h1; hv.z = *(uint*)&h2; hv.w = *(uint*)&h3;
        ((uint4*)g_xh)[(size_t)row * 16 + hl] = hv;
    } else {
        float s  = (v0.x + v0.y + v0.z + v0.w) + (v1.x + v1.y + v1.z + v1.w);
        float s2 = (v0.x * v0.x + v0.y * v0.y + v0.z * v0.z + v0.w * v0.w)
                 + (v1.x * v1.x + v1.y * v1.y + v1.z * v1.z + v1.w * v1.w);
        #pragma unroll
        for (int o = 8; o; o >>= 1) {
            s  += __shfl_xor_sync(0xffffffffu, s, o);
            s2 += __shfl_xor_sync(0xffffffffu, s2, o);
        }
        float mean = s * (1.0f / 128.0f);
        float var = s2 * (1.0f / 128.0f) - mean * mean;
        float rstd = rsqrtf(var + 1e-5f);
        const float4* g4 = (const float4*)lng;
        const float4* lb4 = (const float4*)lnb;
        float4 gg0 = g4[hl * 2], gg1 = g4[hl * 2 + 1];
        float4 lb0 = lb4[hl * 2], lb1 = lb4[hl * 2 + 1];
        float4 o0, o1;
        o0.x = (v0.x - mean) * rstd * gg0.x + lb0.x;
        o0.y = (v0.y - mean) * rstd * gg0.y + lb0.y;
        o0.z = (v0.z - mean) * rstd * gg0.z + lb0.z;
        o0.w = (v0.w - mean) * rstd * gg0.w + lb0.w;
        o1.x = (v1.x - mean) * rstd * gg1.x + lb1.x;
        o1.y = (v1.y - mean) * rstd * gg1.y + lb1.y;
        o1.z = (v1.z - mean) * rstd * gg1.z + lb1.z;
        o1.w = (v1.w - mean) * rstd * gg1.w + lb1.w;
        ((float4*)out)[(size_t)row * 32 + hl * 2] = o0;
        ((float4*)out)[(size_t)row * 32 + hl * 2 + 1] = o1;
    }
}

// ---------------- launcher --------------------------------------------------
static cudaStream_t g_s1 = nullptr;
static cudaEvent_t  g_evFork = nullptr, g_evScan = nullptr, g_evFill = nullptr;

extern "C" void kernel_launch(void* const* d_in, const int* in_sizes, int n_in,
                              void* d_out, int out_size) {
    const float* llm = (const float*)d_in[0];
    const int*   ids = (const int*)d_in[1];
    const int*   ei  = (const int*)d_in[2];
    const float* pW  = (const float*)d_in[3];
    const float* pb  = (const float*)d_in[4];
    const float* emb = (const float*)d_in[5];
    const float* gW  = (const float*)d_in[6];
    const float* gb  = (const float*)d_in[7];
    const float* lg  = (const float*)d_in[8];
    const float* lb  = (const float*)d_in[9];
    const int* src = ei;
    const int* dst = ei + EE;

    const int MB = (NN + 127) / 128;
    const int HB = (NN + 15) / 16;
    const int EB4 = (EE / 4 + 255) / 256;

    if (g_s1 == nullptr) {
        cudaStreamCreateWithFlags(&g_s1, cudaStreamNonBlocking);
        cudaEventCreateWithFlags(&g_evFork, cudaEventDisableTiming);
        cudaEventCreateWithFlags(&g_evScan, cudaEventDisableTiming);
        cudaEventCreateWithFlags(&g_evFill, cudaEventDisableTiming);
    }

    uint* d_WpF = nullptr; cudaGetSymbolAddress((void**)&d_WpF, g_WpF);
    uint* d_WgH = nullptr; cudaGetSymbolAddress((void**)&d_WgH, g_WgH);

    // ---- fork: gcn frag prep (+cnt zero) + CSR chain on side stream ----
    cudaEventRecord(g_evFork, 0);
    cudaStreamWaitEvent(g_s1, g_evFork, 0);

    prep_gcn_k<<<(NN + 255) / 256, 256, 0, g_s1>>>(gW);  // zeroes g_cnt too
    count_k<<<EB4, 256, 0, g_s1>>>(dst);
    scan1_k<<<NSCAN, 1024, 0, g_s1>>>();
    scan2_k<<<1, 32, 0, g_s1>>>();
    scan3_k<<<NSCAN, 1024, 0, g_s1>>>();
    cudaEventRecord(g_evScan, g_s1);   // covers prep_gcn + dis
    fill_k<<<EB4, 256, 0, g_s1>>>(src, dst);
    cudaEventRecord(g_evFill, g_s1);

    // ---- main stream ----
    prep_proj_k<<<(PROJ_FRAG_WORDS + 255) / 256, 256>>>(pW);
    proj_gemm_k<<<MB, 256>>>(llm, d_WpF, pb, ids, emb);

    cudaStreamWaitEvent(0, g_evScan, 0);
    gcn_gemm_k<<<MB, 256>>>(d_WgH);
    cudaStreamWaitEvent(0, g_evFill, 0);
    agg_k<false><<<HB, 256>>>(gb, nullptr, nullptr, nullptr);

    gcn_gemm_k<<<MB, 256>>>(d_WgH + GCNH_WORDS);
    agg_k<true><<<HB, 256>>>(gb + HID, lg, lb, (float*)d_out);
}

// round 15
// speedup vs baseline: 1.1772x; 1.0002x over previous
#include <cuda_runtime.h>
#include <cuda_fp16.h>

#define NN 50000
#define EE 600000
#define LLM 640
#define HID 128
#define PO 112
#define SD 16

typedef unsigned int uint;

#define PROJ_ITS 20
#define ITER_WORDS 4096
#define PROJ_FRAG_WORDS (PROJ_ITS * ITER_WORDS)
#define GCNH_WORDS 8192          // fp16 B image words per layer

#define SCAN_CHUNK 4096
#define NSCAN ((NN + SCAN_CHUNK - 1) / SCAN_CHUNK)   // 13

// ---------------- scratch (static device globals; no allocation) ------------
__device__ float  g_x[(size_t)NN * HID];
__device__ __align__(16) __half g_xh[(size_t)NN * HID];   // fp16 mirror (layer-1 A)
__device__ __align__(16) __half g_xwh[(size_t)NN * HID];  // xw fp16 (UNSCALED)
__device__ float  g_dis[NN];
__device__ __align__(16) int g_cnt[NN];
__device__ int    g_rowptr[NN + 1];
__device__ __align__(16) int g_pos[NN];
__device__ __align__(16) int g_col[EE];
__device__ int    g_bsum[NSCAN];
__device__ int    g_boff[NSCAN];
__device__ __align__(16) uint g_WpF[PROJ_FRAG_WORDS];
__device__ __align__(16) uint g_WgH[2][GCNH_WORDS];

__device__ __forceinline__ uint f2tf32(float x) {
    uint r;
    asm("cvt.rna.tf32.f32 %0, %1;" : "=r"(r) : "f"(x));
    return r;
}
__device__ __forceinline__ float4 h8_to_f4(uint a, uint b) {
    __half2 ha = *(__half2*)&a, hb = *(__half2*)&b;
    float2 fa = __half22float2(ha), fb = __half22float2(hb);
    return make_float4(fa.x, fa.y, fb.x, fb.y);
}

// proj fragment layout: word = ((ntile*4 + k8)*64) + lane*2 + jj
__global__ void prep_proj_k(const float* __restrict__ pW) {
    int i = blockIdx.x * blockDim.x + threadIdx.x;
    if (i < PROJ_FRAG_WORDS) {
        int it = i >> 12, word = i & 4095;
        int blk = word >> 6, rem = word & 63;
        int ntile = blk >> 2, k8 = blk & 3;
        int lane = rem >> 1, jj = rem & 1;
        int k = it * 32 + k8 * 8 + jj * 4 + (lane & 3);
        int n = ntile * 8 + (lane >> 2);
        float v = (n < PO) ? pW[k * PO + n] : 0.0f;
        g_WpF[i] = f2tf32(v);
    }
}

// gcn fp16 B image + zero counters (side stream)
__global__ void prep_gcn_k(const float* __restrict__ gW) {
    int i = blockIdx.x * blockDim.x + threadIdx.x;
    if (i < NN) g_cnt[i] = 0;
    if (i < 2 * GCNH_WORDS) {
        int layer = i >> 13;
        int w = i & (GCNH_WORDS - 1);
        int it = w >> 11, word = w & 2047;
        int blk = word >> 6, rem = word & 63;
        int nt = blk >> 1, s = blk & 1;
        int lane = rem >> 1, j = rem & 1;
        int k = it * 32 + s * 16 + (lane & 3) * 2 + j * 8;
        int n = nt * 8 + (lane >> 2);
        const float* Wl = gW + (size_t)layer * HID * HID;
        __half2 h = __floats2half2_rn(Wl[k * HID + n], Wl[(k + 1) * HID + n]);
        g_WgH[layer][w] = *(uint*)&h;
    }
}

// ---------------- CSR build (side stream) -----------------------------------
__global__ void count_k(const int* __restrict__ dst) {
    int e0 = (blockIdx.x * blockDim.x + threadIdx.x) * 4;
    if (e0 < EE) {
        int4 d = *(const int4*)(dst + e0);
        atomicAdd(&g_cnt[d.x], 1);
        atomicAdd(&g_cnt[d.y], 1);
        atomicAdd(&g_cnt[d.z], 1);
        atomicAdd(&g_cnt[d.w], 1);
    }
}

__global__ void scan1_k() {
    __shared__ int warp_tot[32];
    int tid = threadIdx.x, lane = tid & 31, w = tid >> 5;
    int i0 = blockIdx.x * SCAN_CHUNK + tid * 4;
    int4 v = make_int4(0, 0, 0, 0);
    if (i0 < NN) v = *(const int4*)(g_cnt + i0);
    int s = v.x + v.y + v.z + v.w;
    int x = s;
    #pragma unroll
    for (int o = 1; o < 32; o <<= 1) {
        int y = __shfl_up_sync(0xffffffffu, x, o);
        if (lane >= o) x += y;
    }
    if (lane == 31) warp_tot[w] = x;
    __syncthreads();
    if (w == 0) {
        int t = warp_tot[lane];
        #pragma unroll
        for (int o = 1; o < 32; o <<= 1) {
            int y = __shfl_up_sync(0xffffffffu, t, o);
            if (lane >= o) t += y;
        }
        warp_tot[lane] = t;
    }
    __syncthreads();
    int woff = (w > 0) ? warp_tot[w - 1] : 0;
    int incl = x + woff;
    int excl = incl - s;
    if (i0 < NN) {
        int4 li;
        li.x = excl + v.x;
        li.y = li.x + v.y;
        li.z = li.y + v.z;
        li.w = li.z + v.w;
        *(int4*)(g_pos + i0) = li;
    }
    if (tid == 1023) g_bsum[blockIdx.x] = incl;
}

__global__ void scan2_k() {
    int lane = threadIdx.x;
    int v = (lane < NSCAN) ? g_bsum[lane] : 0;
    int x = v;
    #pragma unroll
    for (int o = 1; o < 32; o <<= 1) {
        int y = __shfl_up_sync(0xffffffffu, x, o);
        if (lane >= o) x += y;
    }
    if (lane < NSCAN) g_boff[lane] = x - v;
    if (lane == 0) g_rowptr[0] = 0;
}

__global__ void scan3_k() {
    int tid = threadIdx.x;
    int i0 = blockIdx.x * SCAN_CHUNK + tid * 4;
    if (i0 >= NN) return;
    int off = g_boff[blockIdx.x];
    int4 v  = *(const int4*)(g_cnt + i0);
    int4 li = *(const int4*)(g_pos + i0);
    int4 incl = make_int4(li.x + off, li.y + off, li.z + off, li.w + off);
    g_rowptr[i0 + 1] = incl.x;
    g_rowptr[i0 + 2] = incl.y;
    g_rowptr[i0 + 3] = incl.z;
    g_rowptr[i0 + 4] = incl.w;
    *(int4*)(g_pos + i0) = make_int4(incl.x - v.x, incl.y - v.y,
                                     incl.z - v.z, incl.w - v.w);
    g_dis[i0 + 0] = rsqrtf(1.0f + (float)v.x);
    g_dis[i0 + 1] = rsqrtf(1.0f + (float)v.y);
    g_dis[i0 + 2] = rsqrtf(1.0f + (float)v.z);
    g_dis[i0 + 3] = rsqrtf(1.0f + (float)v.w);
}

__global__ void fill_k(const int* __restrict__ src, const int* __restrict__ dst) {
    int e0 = (blockIdx.x * blockDim.x + threadIdx.x) * 4;
    if (e0 < EE) {
        int4 d = *(const int4*)(dst + e0);
        int4 s = *(const int4*)(src + e0);
        int p0 = atomicAdd(&g_pos[d.x], 1);
        int p1 = atomicAdd(&g_pos[d.y], 1);
        int p2 = atomicAdd(&g_pos[d.z], 1);
        int p3 = atomicAdd(&g_pos[d.w], 1);
        g_col[p0] = s.x; g_col[p1] = s.y; g_col[p2] = s.z; g_col[p3] = s.w;
    }
}

// ---------------- fused proj (tf32) + gemm0 (fp16) --------------------------
#define BSA 132
#define ASZ (32 * BSA)      // 4224 words
#define BSZ 4096
#define AHROW 68            // fp16 x tile row stride in words (64 data + 4 pad)
#define BSZH 2048

union SmemU {
    struct { uint As[2][ASZ]; uint Bs[2][BSZ]; } p;          // 66,560 B
    struct { uint Ah[128 * AHROW]; uint Bg[2][BSZH]; } g;    // 51,200 B
};

__global__ __launch_bounds__(256, 2) void proj_gcn0_k(const float* __restrict__ A,
                                                      const uint* __restrict__ WF,
                                                      const float* __restrict__ bias,
                                                      const int* __restrict__ ids,
                                                      const float* __restrict__ emb,
                                                      const uint* __restrict__ WgH) {
    __shared__ __align__(16) SmemU sm;
    int tid = threadIdx.x;
    int lane = tid & 31, wid = tid >> 5;
    int warp_m = wid >> 2;
    int warp_n = wid & 3;
    int row0 = blockIdx.x * 128;
    const int NT = LLM / 32;

    // ================= phase 1: proj tf32 GEMM =================
    {
        float acc[4][4][4];
        #pragma unroll
        for (int mt = 0; mt < 4; mt++)
            #pragma unroll
            for (int nt = 0; nt < 4; nt++)
                #pragma unroll
                for (int j = 0; j < 4; j++) acc[mt][nt][j] = 0.0f;

        float4 va[4];

        auto loadA = [&](int k0) {
            #pragma unroll
            for (int i = 0; i < 4; i++) {
                int f = tid + i * 256;
                int r = f >> 3, c = (f & 7) * 4;
                int gr = row0 + r;
                va[i] = make_float4(0.f, 0.f, 0.f, 0.f);
                if (gr < NN) va[i] = *(const float4*)(A + (size_t)gr * LLM + k0 + c);
            }
        };
        auto storeA = [&](int buf) {
            #pragma unroll
            for (int i = 0; i < 4; i++) {
                int f = tid + i * 256;
                int r = f >> 3, c = (f & 7) * 4;
                int mtile = r >> 4, rloc = r & 15;
                int j = (rloc >> 3) + 2 * ((c >> 2) & 1);
                int tb = (rloc & 7) * 4;
                uint* dst = sm.p.As[buf] + ((mtile << 2) + (c >> 3)) * BSA + j;
                dst[(tb + 0) * 4] = __float_as_uint(va[i].x);
                dst[(tb + 1) * 4] = __float_as_uint(va[i].y);
                dst[(tb + 2) * 4] = __float_as_uint(va[i].z);
                dst[(tb + 3) * 4] = __float_as_uint(va[i].w);
            }
        };
        auto stageB = [&](int it, int buf) {
            const uint* src = WF + (size_t)it * ITER_WORDS + tid * 16;
            uint sm32 = (uint)__cvta_generic_to_shared(sm.p.Bs[buf] + tid * 16);
            #pragma unroll
            for (int i = 0; i < 4; i++)
                asm volatile("cp.async.ca.shared.global [%0], [%1], 16;"
                             :: "r"(sm32 + i * 16), "l"(src + i * 4));
            asm volatile("cp.async.commit_group;");
        };

        loadA(0);
        stageB(0, 0);
        storeA(0);
        asm volatile("cp.async.wait_group 0;" ::: "memory");
        __syncthreads();

        for (int it = 0; it < NT; it++) {
            int cur = it & 1;
            if (it + 1 < NT) {
                stageB(it + 1, cur ^ 1);
                loadA((it + 1) * 32);
            }

            #pragma unroll
            for (int k8 = 0; k8 < 4; k8++) {
                uint4 a[4];
                uint2 b[4];
                #pragma unroll
                for (int mt = 0; mt < 4; mt++)
                    a[mt] = *(const uint4*)(sm.p.As[cur] + (((warp_m * 4 + mt) << 2) + k8) * BSA + lane * 4);
                #pragma unroll
                for (int nt = 0; nt < 4; nt++)
                    b[nt] = *(const uint2*)(sm.p.Bs[cur] + (((warp_n * 4 + nt) << 2) + k8) * 64 + lane * 2);
                #pragma unroll
                for (int mt = 0; mt < 4; mt++)
                    #pragma unroll
                    for (int nt = 0; nt < 4; nt++) {
                        asm volatile(
                            "mma.sync.aligned.m16n8k8.row.col.f32.tf32.tf32.f32 "
                            "{%0,%1,%2,%3}, {%4,%5,%6,%7}, {%8,%9}, {%0,%1,%2,%3};"
                            : "+f"(acc[mt][nt][0]), "+f"(acc[mt][nt][1]),
                              "+f"(acc[mt][nt][2]), "+f"(acc[mt][nt][3])
                            : "r"(a[mt].x), "r"(a[mt].y), "r"(a[mt].z), "r"(a[mt].w),
                              "r"(b[nt].x), "r"(b[nt].y));
                    }
            }

            if (it + 1 < NT) {
                storeA(cur ^ 1);
                asm volatile("cp.async.wait_group 0;" ::: "memory");
                __syncthreads();
            }
        }
        __syncthreads();   // all warps done with As/Bs before union reuse

        // epilogue: x fp32 -> global; fp16 -> smem Ah (row stride 68 words)
        #pragma unroll
        for (int mt = 0; mt < 4; mt++) {
            int gr0 = row0 + warp_m * 64 + mt * 16 + (lane >> 2);
            int gr1 = gr0 + 8;
            int rl0 = warp_m * 64 + mt * 16 + (lane >> 2);
            #pragma unroll
            for (int nt = 0; nt < 4; nt++) {
                int col = warp_n * 32 + nt * 8 + (lane & 3) * 2;
                float2 v0, v1;
                if (col < PO) {
                    float b0 = bias[col], b1 = bias[col + 1];
                    v0 = make_float2(acc[mt][nt][0] + b0, acc[mt][nt][1] + b1);
                    v1 = make_float2(acc[mt][nt][2] + b0, acc[mt][nt][3] + b1);
                } else {
                    int t = col - PO;
                    v0 = (gr0 < NN) ? *(const float2*)(emb + ids[gr0] * SD + t)
                                    : make_float2(0.f, 0.f);
                    v1 = (gr1 < NN) ? *(const float2*)(emb + ids[gr1] * SD + t)
                                    : make_float2(0.f, 0.f);
                }
                __half2 h0 = __floats2half2_rn(v0.x, v0.y);
                __half2 h1 = __floats2half2_rn(v1.x, v1.y);
                sm.g.Ah[rl0 * AHROW + (col >> 1)] = *(uint*)&h0;
                sm.g.Ah[(rl0 + 8) * AHROW + (col >> 1)] = *(uint*)&h1;
                if (gr0 < NN) *(float2*)(g_x + (size_t)gr0 * 128 + col) = v0;
                if (gr1 < NN) *(float2*)(g_x + (size_t)gr1 * 128 + col) = v1;
            }
        }
    }
    __syncthreads();

    // ================= phase 2: gcn0 fp16 GEMM (A from smem) =================
    {
        float acc[4][4][4];
        #pragma unroll
        for (int mt = 0; mt < 4; mt++)
            #pragma unroll
            for (int nt = 0; nt < 4; nt++)
                #pragma unroll
                for (int j = 0; j < 4; j++) acc[mt][nt][j] = 0.0f;

        auto stageBg = [&](int it, int buf) {
            const uint* src = WgH + it * BSZH + tid * 8;
            uint sm32 = (uint)__cvta_generic_to_shared(sm.g.Bg[buf] + tid * 8);
            #pragma unroll
            for (int i = 0; i < 2; i++)
                asm volatile("cp.async.ca.shared.global [%0], [%1], 16;"
                             :: "r"(sm32 + i * 16), "l"(src + i * 4));
            asm volatile("cp.async.commit_group;");
        };

        stageBg(0, 0);
        asm volatile("cp.async.wait_group 0;" ::: "memory");
        __syncthreads();

        for (int it = 0; it < 4; it++) {
            int cur = it & 1;
            if (it + 1 < 4) stageBg(it + 1, cur ^ 1);

            #pragma unroll
            for (int s = 0; s < 2; s++) {
                uint a[4][4];
                #pragma unroll
                for (int mt = 0; mt < 4; mt++) {
                    int base = (warp_m * 64 + mt * 16 + (lane >> 2)) * AHROW
                             + it * 16 + s * 8 + (lane & 3);
                    a[mt][0] = sm.g.Ah[base];
                    a[mt][1] = sm.g.Ah[base + 8 * AHROW];
                    a[mt][2] = sm.g.Ah[base + 4];
                    a[mt][3] = sm.g.Ah[base + 8 * AHROW + 4];
                }
                uint2 b[4];
                #pragma unroll
                for (int ntl = 0; ntl < 4; ntl++) {
                    int nt = warp_n * 4 + ntl;
                    b[ntl] = *(const uint2*)(sm.g.Bg[cur] + (nt * 2 + s) * 64 + lane * 2);
                }
                #pragma unroll
                for (int mt = 0; mt < 4; mt++)
                    #pragma unroll
                    for (int ntl = 0; ntl < 4; ntl++) {
                        asm volatile(
                            "mma.sync.aligned.m16n8k16.row.col.f32.f16.f16.f32 "
                            "{%0,%1,%2,%3}, {%4,%5,%6,%7}, {%8,%9}, {%0,%1,%2,%3};"
                            : "+f"(acc[mt][ntl][0]), "+f"(acc[mt][ntl][1]),
                              "+f"(acc[mt][ntl][2]), "+f"(acc[mt][ntl][3])
                            : "r"(a[mt][0]), "r"(a[mt][1]), "r"(a[mt][2]), "r"(a[mt][3]),
                              "r"(b[ntl].x), "r"(b[ntl].y));
                    }
            }

            if (it + 1 < 4) {
                asm volatile("cp.async.wait_group 0;" ::: "memory");
                __syncthreads();
            }
        }

        // epilogue: xw fp16 UNSCALED
        #pragma unroll
        for (int mt = 0; mt < 4; mt++) {
            int gr0 = row0 + warp_m * 64 + mt * 16 + (lane >> 2);
            int gr1 = gr0 + 8;
            #pragma unroll
            for (int nt = 0; nt < 4; nt++) {
                int col = warp_n * 32 + nt * 8 + (lane & 3) * 2;
                if (gr0 < NN)
                    *(__half2*)(g_xwh + (size_t)gr0 * 128 + col) =
                        __floats2half2_rn(acc[mt][nt][0], acc[mt][nt][1]);
                if (gr1 < NN)
                    *(__half2*)(g_xwh + (size_t)gr1 * 128 + col) =
                        __floats2half2_rn(acc[mt][nt][2], acc[mt][nt][3]);
            }
        }
    }
}

// ---------------- GCN GEMM layer 1: fp16, A from g_xh via cp.async ----------
#define AROW 36
#define ASZH (128 * AROW)

__global__ __launch_bounds__(256, 2) void gcn_gemm_k(const uint* __restrict__ WF) {
    __shared__ __align__(16) uint As[2][ASZH];
    __shared__ __align__(16) uint Bs[2][BSZH];
    int tid = threadIdx.x;
    int lane = tid & 31, wid = tid >> 5;
    int warp_m = wid >> 2;
    int warp_n = wid & 3;
    int row0 = blockIdx.x * 128;

    float acc[4][4][4];
    #pragma unroll
    for (int mt = 0; mt < 4; mt++)
        #pragma unroll
        for (int nt = 0; nt < 4; nt++)
            #pragma unroll
            for (int j = 0; j < 4; j++) acc[mt][nt][j] = 0.0f;

    auto stageA = [&](int it, int buf) {
        #pragma unroll
        for (int i = 0; i < 2; i++) {
            int c = tid + i * 256;
            int r = c >> 2, q = c & 3;
            int gr = row0 + r;
            const __half* src = g_xh + (size_t)(gr < NN ? gr : NN - 1) * 128 + it * 32 + q * 8;
            uint sm = (uint)__cvta_generic_to_shared(As[buf] + r * AROW + q * 4);
            asm volatile("cp.async.ca.shared.global [%0], [%1], 16;"
                         :: "r"(sm), "l"(src));
        }
    };
    auto stageB = [&](int it, int buf) {
        const uint* src = WF + it * BSZH + tid * 8;
        uint sm = (uint)__cvta_generic_to_shared(Bs[buf] + tid * 8);
        #pragma unroll
        for (int i = 0; i < 2; i++)
            asm volatile("cp.async.ca.shared.global [%0], [%1], 16;"
                         :: "r"(sm + i * 16), "l"(src + i * 4));
    };

    stageA(0, 0);
    stageB(0, 0);
    asm volatile("cp.async.commit_group;");
    asm volatile("cp.async.wait_group 0;" ::: "memory");
    __syncthreads();

    for (int it = 0; it < 4; it++) {
        int cur = it & 1;
        if (it + 1 < 4) {
            stageA(it + 1, cur ^ 1);
            stageB(it + 1, cur ^ 1);
            asm volatile("cp.async.commit_group;");
        }

        #pragma unroll
        for (int s = 0; s < 2; s++) {
            uint a[4][4];
            #pragma unroll
            for (int mt = 0; mt < 4; mt++) {
                int base = (warp_m * 64 + mt * 16 + (lane >> 2)) * AROW + s * 8 + (lane & 3);
                a[mt][0] = As[cur][base];
                a[mt][1] = As[cur][base + 8 * AROW];
                a[mt][2] = As[cur][base + 4];
                a[mt][3] = As[cur][base + 8 * AROW + 4];
            }
            uint2 b[4];
            #pragma unroll
            for (int ntl = 0; ntl < 4; ntl++) {
                int nt = warp_n * 4 + ntl;
                b[ntl] = *(const uint2*)(Bs[cur] + (nt * 2 + s) * 64 + lane * 2);
            }
            #pragma unroll
            for (int mt = 0; mt < 4; mt++)
                #pragma unroll
                for (int ntl = 0; ntl < 4; ntl++) {
                    asm volatile(
                        "mma.sync.aligned.m16n8k16.row.col.f32.f16.f16.f32 "
                        "{%0,%1,%2,%3}, {%4,%5,%6,%7}, {%8,%9}, {%0,%1,%2,%3};"
                        : "+f"(acc[mt][ntl][0]), "+f"(acc[mt][ntl][1]),
                          "+f"(acc[mt][ntl][2]), "+f"(acc[mt][ntl][3])
                        : "r"(a[mt][0]), "r"(a[mt][1]), "r"(a[mt][2]), "r"(a[mt][3]),
                          "r"(b[ntl].x), "r"(b[ntl].y));
                }
        }

        if (it + 1 < 4) {
            asm volatile("cp.async.wait_group 0;" ::: "memory");
            __syncthreads();
        }
    }

    // epilogue: xw fp16 UNSCALED
    #pragma unroll
    for (int mt = 0; mt < 4; mt++) {
        int gr0 = row0 + warp_m * 64 + mt * 16 + (lane >> 2);
        int gr1 = gr0 + 8;
        #pragma unroll
        for (int nt = 0; nt < 4; nt++) {
            int col = warp_n * 32 + nt * 8 + (lane & 3) * 2;
            if (gr0 < NN)
                *(__half2*)(g_xwh + (size_t)gr0 * 128 + col) =
                    __floats2half2_rn(acc[mt][nt][0], acc[mt][nt][1]);
            if (gr1 < NN)
                *(__half2*)(g_xwh + (size_t)gr1 * 128 + col) =
                    __floats2half2_rn(acc[mt][nt][2], acc[mt][nt][3]);
        }
    }
}

// ---------------- aggregation: half-warp per row; per-edge dis weight -------
template<bool LAST>
__global__ void agg_k(const float* __restrict__ bias,
                      const float* __restrict__ lng,
                      const float* __restrict__ lnb,
                      float* __restrict__ out) {
    int warp = threadIdx.x >> 5, lane = threadIdx.x & 31;
    int half = lane >> 4, hl = lane & 15;
    int row = blockIdx.x * 16 + warp * 2 + half;
    if (row >= NN) return;
    const uint4* xw4 = (const uint4*)g_xwh;
    float d = g_dis[row];
    uint4 ps = xw4[(size_t)row * 16 + hl];
    float4 u0 = h8_to_f4(ps.x, ps.y);
    float4 u1 = h8_to_f4(ps.z, ps.w);
    float4 a0 = make_float4(d * u0.x, d * u0.y, d * u0.z, d * u0.w);
    float4 a1 = make_float4(d * u1.x, d * u1.y, d * u1.z, d * u1.w);
    int e = g_rowptr[row], end = g_rowptr[row + 1];
    for (; e + 8 <= end; e += 8) {
        int s0 = g_col[e],     s1 = g_col[e + 1], s2 = g_col[e + 2], s3 = g_col[e + 3];
        int s4 = g_col[e + 4], s5 = g_col[e + 5], s6 = g_col[e + 6], s7 = g_col[e + 7];
        uint4 q0 = xw4[(size_t)s0 * 16 + hl];
        uint4 q1 = xw4[(size_t)s1 * 16 + hl];
        uint4 q2 = xw4[(size_t)s2 * 16 + hl];
        uint4 q3 = xw4[(size_t)s3 * 16 + hl];
        uint4 q4 = xw4[(size_t)s4 * 16 + hl];
        uint4 q5 = xw4[(size_t)s5 * 16 + hl];
        uint4 q6 = xw4[(size_t)s6 * 16 + hl];
        uint4 q7 = xw4[(size_t)s7 * 16 + hl];
        float w0 = g_dis[s0], w1 = g_dis[s1], w2 = g_dis[s2], w3 = g_dis[s3];
        float w4 = g_dis[s4], w5 = g_dis[s5], w6 = g_dis[s6], w7 = g_dis[s7];
        float4 u;
        u = h8_to_f4(q0.x, q0.y); a0.x += w0*u.x; a0.y += w0*u.y; a0.z += w0*u.z; a0.w += w0*u.w;
        u = h8_to_f4(q0.z, q0.w); a1.x += w0*u.x; a1.y += w0*u.y; a1.z += w0*u.z; a1.w += w0*u.w;
        u = h8_to_f4(q1.x, q1.y); a0.x += w1*u.x; a0.y += w1*u.y; a0.z += w1*u.z; a0.w += w1*u.w;
        u = h8_to_f4(q1.z, q1.w); a1.x += w1*u.x; a1.y += w1*u.y; a1.z += w1*u.z; a1.w += w1*u.w;
        u = h8_to_f4(q2.x, q2.y); a0.x += w2*u.x; a0.y += w2*u.y; a0.z += w2*u.z; a0.w += w2*u.w;
        u = h8_to_f4(q2.z, q2.w); a1.x += w2*u.x; a1.y += w2*u.y; a1.z += w2*u.z; a1.w += w2*u.w;
        u = h8_to_f4(q3.x, q3.y); a0.x += w3*u.x; a0.y += w3*u.y; a0.z += w3*u.z; a0.w += w3*u.w;
        u = h8_to_f4(q3.z, q3.w); a1.x += w3*u.x; a1.y += w3*u.y; a1.z += w3*u.z; a1.w += w3*u.w;
        u = h8_to_f4(q4.x, q4.y); a0.x += w4*u.x; a0.y += w4*u.y; a0.z += w4*u.z; a0.w += w4*u.w;
        u = h8_to_f4(q4.z, q4.w); a1.x += w4*u.x; a1.y += w4*u.y; a1.z += w4*u.z; a1.w += w4*u.w;
        u = h8_to_f4(q5.x, q5.y); a0.x += w5*u.x; a0.y += w5*u.y; a0.z += w5*u.z; a0.w += w5*u.w;
        u = h8_to_f4(q5.z, q5.w); a1.x += w5*u.x; a1.y += w5*u.y; a1.z += w5*u.z; a1.w += w5*u.w;
        u = h8_to_f4(q6.x, q6.y); a0.x += w6*u.x; a0.y += w6*u.y; a0.z += w6*u.z; a0.w += w6*u.w;
        u = h8_to_f4(q6.z, q6.w); a1.x += w6*u.x; a1.y += w6*u.y; a1.z += w6*u.z; a1.w += w6*u.w;
        u = h8_to_f4(q7.x, q7.y); a0.x += w7*u.x; a0.y += w7*u.y; a0.z += w7*u.z; a0.w += w7*u.w;
        u = h8_to_f4(q7.z, q7.w); a1.x += w7*u.x; a1.y += w7*u.y; a1.z += w7*u.z; a1.w += w7*u.w;
    }
    for (; e < end; e++) {
        int s = g_col[e];
        uint4 q = xw4[(size_t)s * 16 + hl];
        float w = g_dis[s];
        float4 u;
        u = h8_to_f4(q.x, q.y); a0.x += w*u.x; a0.y += w*u.y; a0.z += w*u.z; a0.w += w*u.w;
        u = h8_to_f4(q.z, q.w); a1.x += w*u.x; a1.y += w*u.y; a1.z += w*u.z; a1.w += w*u.w;
    }
    const float4* b4 = (const float4*)bias;
    float4 bb0 = b4[hl * 2], bb1 = b4[hl * 2 + 1];
    const float4* x4 = (const float4*)g_x;
    float4 x0 = x4[(size_t)row * 32 + hl * 2];
    float4 x1 = x4[(size_t)row * 32 + hl * 2 + 1];
    float4 v0, v1;
    v0.x = x0.x + fmaxf(d * a0.x + bb0.x, 0.f);
    v0.y = x0.y + fmaxf(d * a0.y + bb0.y, 0.f);
    v0.z = x0.z + fmaxf(d * a0.z + bb0.z, 0.f);
    v0.w = x0.w + fmaxf(d * a0.w + bb0.w, 0.f);
    v1.x = x1.x + fmaxf(d * a1.x + bb1.x, 0.f);
    v1.y = x1.y + fmaxf(d * a1.y + bb1.y, 0.f);
    v1.z = x1.z + fmaxf(d * a1.z + bb1.z, 0.f);
    v1.w = x1.w + fmaxf(d * a1.w + bb1.w, 0.f);
    if (!LAST) {
        ((float4*)g_x)[(size_t)row * 32 + hl * 2] = v0;
        ((float4*)g_x)[(size_t)row * 32 + hl * 2 + 1] = v1;
        uint4 hv;
        __half2 h0 = __floats2half2_rn(v0.x, v0.y);
        __half2 h1 = __floats2half2_rn(v0.z, v0.w);
        __half2 h2 = __floats2half2_rn(v1.x, v1.y);
        __half2 h3 = __floats2half2_rn(v1.z, v1.w);
        hv.x = *(uint*)&h0; hv.y = *(uint*)&h1; hv.z = *(uint*)&h2; hv.w = *(uint*)&h3;
        ((uint4*)g_xh)[(size_t)row * 16 + hl] = hv;
    } else {
        float s  = (v0.x + v0.y + v0.z + v0.w) + (v1.x + v1.y + v1.z + v1.w);
        float s2 = (v0.x * v0.x + v0.y * v0.y + v0.z * v0.z + v0.w * v0.w)
                 + (v1.x * v1.x + v1.y * v1.y + v1.z * v1.z + v1.w * v1.w);
        #pragma unroll
        for (int o = 8; o; o >>= 1) {
            s  += __shfl_xor_sync(0xffffffffu, s, o);
            s2 += __shfl_xor_sync(0xffffffffu, s2, o);
        }
        float mean = s * (1.0f / 128.0f);
        float var = s2 * (1.0f / 128.0f) - mean * mean;
        float rstd = rsqrtf(var + 1e-5f);
        const float4* g4 = (const float4*)lng;
        const float4* lb4 = (const float4*)lnb;
        float4 gg0 = g4[hl * 2], gg1 = g4[hl * 2 + 1];
        float4 lb0 = lb4[hl * 2], lb1 = lb4[hl * 2 + 1];
        float4 o0, o1;
        o0.x = (v0.x - mean) * rstd * gg0.x + lb0.x;
        o0.y = (v0.y - mean) * rstd * gg0.y + lb0.y;
        o0.z = (v0.z - mean) * rstd * gg0.z + lb0.z;
        o0.w = (v0.w - mean) * rstd * gg0.w + lb0.w;
        o1.x = (v1.x - mean) * rstd * gg1.x + lb1.x;
        o1.y = (v1.y - mean) * rstd * gg1.y + lb1.y;
        o1.z = (v1.z - mean) * rstd * gg1.z + lb1.z;
        o1.w = (v1.w - mean) * rstd * gg1.w + lb1.w;
        ((float4*)out)[(size_t)row * 32 + hl * 2] = o0;
        ((float4*)out)[(size_t)row * 32 + hl * 2 + 1] = o1;
    }
}

// ---------------- launcher --------------------------------------------------
static cudaStream_t g_s1 = nullptr;
static cudaEvent_t  g_evFork = nullptr, g_evPrep = nullptr, g_evFill = nullptr;

extern "C" void kernel_launch(void* const* d_in, const int* in_sizes, int n_in,
                              void* d_out, int out_size) {
    const float* llm = (const float*)d_in[0];
    const int*   ids = (const int*)d_in[1];
    const int*   ei  = (const int*)d_in[2];
    const float* pW  = (const float*)d_in[3];
    const float* pb  = (const float*)d_in[4];
    const float* emb = (const float*)d_in[5];
    const float* gW  = (const float*)d_in[6];
    const float* gb  = (const float*)d_in[7];
    const float* lg  = (const float*)d_in[8];
    const float* lb  = (const float*)d_in[9];
    const int* src = ei;
    const int* dst = ei + EE;

    const int MB = (NN + 127) / 128;
    const int HB = (NN + 15) / 16;
    const int EB4 = (EE / 4 + 255) / 256;

    if (g_s1 == nullptr) {
        cudaStreamCreateWithFlags(&g_s1, cudaStreamNonBlocking);
        cudaEventCreateWithFlags(&g_evFork, cudaEventDisableTiming);
        cudaEventCreateWithFlags(&g_evPrep, cudaEventDisableTiming);
        cudaEventCreateWithFlags(&g_evFill, cudaEventDisableTiming);
    }

    uint* d_WpF = nullptr; cudaGetSymbolAddress((void**)&d_WpF, g_WpF);
    uint* d_WgH = nullptr; cudaGetSymbolAddress((void**)&d_WgH, g_WgH);

    // ---- fork: gcn frag prep (+cnt zero) + CSR chain on side stream ----
    cudaEventRecord(g_evFork, 0);
    cudaStreamWaitEvent(g_s1, g_evFork, 0);

    prep_gcn_k<<<(NN + 255) / 256, 256, 0, g_s1>>>(gW);  // zeroes g_cnt too
    cudaEventRecord(g_evPrep, g_s1);
    count_k<<<EB4, 256, 0, g_s1>>>(dst);
    scan1_k<<<NSCAN, 1024, 0, g_s1>>>();
    scan2_k<<<1, 32, 0, g_s1>>>();
    scan3_k<<<NSCAN, 1024, 0, g_s1>>>();
    fill_k<<<EB4, 256, 0, g_s1>>>(src, dst);
    cudaEventRecord(g_evFill, g_s1);

    // ---- main stream: proj frag prep + fused proj+gcn0 ----
    prep_proj_k<<<(PROJ_FRAG_WORDS + 255) / 256, 256>>>(pW);
    cudaStreamWaitEvent(0, g_evPrep, 0);   // g_WgH[0] ready (trivially early)
    proj_gcn0_k<<<MB, 256>>>(llm, d_WpF, pb, ids, emb, d_WgH);

    cudaStreamWaitEvent(0, g_evFill, 0);   // rowptr/col/dis ready
    agg_k<false><<<HB, 256>>>(gb, nullptr, nullptr, nullptr);

    gcn_gemm_k<<<MB, 256>>>(d_WgH + GCNH_WORDS);
    agg_k<true><<<HB, 256>>>(gb + HID, lg, lb, (float*)d_out);
}